// round 1
// baseline (speedup 1.0000x reference)
#include <cuda_runtime.h>
#include <cuda_bf16.h>

// Problem constants (fixed shapes)
#define TOK   100352          // B * H * W = 32 * 56 * 56
#define CIN   384
#define COUT  1152
#define NWIN  2048            // B * 64 windows
#define NHEAD 12

// Scratch for QKV projection result (fp32): 100352 x 1152 = 462 MB
__device__ float g_qkv[(size_t)TOK * COUT];

// ---------------------------------------------------------------------------
// Kernel 1: QKV GEMM  Y = X @ W^T + b
// X: [TOK, 384] row-major, W: [1152, 384] row-major (K contiguous both sides)
// Tiling: BM=128, BN=64, BK=16, 256 threads, 8x4 microtile per thread.
// ---------------------------------------------------------------------------
#define BM 128
#define BN 64
#define BK 16
#define AS_STRIDE 132   // BM + 4 padding (keeps 16B alignment, reduces conflicts)
#define BS_STRIDE 68    // BN + 4

__global__ __launch_bounds__(256) void qkv_gemm(const float* __restrict__ X,
                                                const float* __restrict__ W,
                                                const float* __restrict__ bias) {
    __shared__ float As[BK][AS_STRIDE];
    __shared__ float Bs[BK][BS_STRIDE];

    const int tid = threadIdx.x;
    const int m0 = blockIdx.x * BM;
    const int n0 = blockIdx.y * BN;
    const int ty = tid >> 4;          // 0..15
    const int tx = tid & 15;          // 0..15
    const int row0 = ty * 8;          // 0..120
    const int col0 = tx * 4;          // 0..60

    float acc[8][4];
    #pragma unroll
    for (int i = 0; i < 8; i++)
        #pragma unroll
        for (int j = 0; j < 4; j++) acc[i][j] = 0.0f;

    // A-load mapping: q = tid*2 + l -> row=q>>2 (0..127), kq=q&3
    // B-load mapping: q = tid      -> row=q>>2 (0..63),  kq=q&3
    const int ar  = tid >> 1;          // same row for both l
    const int br  = tid >> 2;
    const int bkq = tid & 3;

    for (int k0 = 0; k0 < CIN; k0 += BK) {
        #pragma unroll
        for (int l = 0; l < 2; l++) {
            int akq = ((tid * 2 + l) & 3);
            float4 va = *reinterpret_cast<const float4*>(
                X + (size_t)(m0 + ar) * CIN + k0 + akq * 4);
            As[akq * 4 + 0][ar] = va.x;
            As[akq * 4 + 1][ar] = va.y;
            As[akq * 4 + 2][ar] = va.z;
            As[akq * 4 + 3][ar] = va.w;
        }
        {
            float4 vb = *reinterpret_cast<const float4*>(
                W + (size_t)(n0 + br) * CIN + k0 + bkq * 4);
            Bs[bkq * 4 + 0][br] = vb.x;
            Bs[bkq * 4 + 1][br] = vb.y;
            Bs[bkq * 4 + 2][br] = vb.z;
            Bs[bkq * 4 + 3][br] = vb.w;
        }
        __syncthreads();

        #pragma unroll
        for (int kk = 0; kk < BK; kk++) {
            float4 a0 = *reinterpret_cast<const float4*>(&As[kk][row0]);
            float4 a1 = *reinterpret_cast<const float4*>(&As[kk][row0 + 4]);
            float4 bv = *reinterpret_cast<const float4*>(&Bs[kk][col0]);
            float a[8] = {a0.x, a0.y, a0.z, a0.w, a1.x, a1.y, a1.z, a1.w};
            float bb[4] = {bv.x, bv.y, bv.z, bv.w};
            #pragma unroll
            for (int i = 0; i < 8; i++)
                #pragma unroll
                for (int j = 0; j < 4; j++)
                    acc[i][j] = fmaf(a[i], bb[j], acc[i][j]);
        }
        __syncthreads();
    }

    float4 bcol = *reinterpret_cast<const float4*>(bias + n0 + col0);
    #pragma unroll
    for (int i = 0; i < 8; i++) {
        float4 o;
        o.x = acc[i][0] + bcol.x;
        o.y = acc[i][1] + bcol.y;
        o.z = acc[i][2] + bcol.z;
        o.w = acc[i][3] + bcol.w;
        *reinterpret_cast<float4*>(
            &g_qkv[(size_t)(m0 + row0 + i) * COUT + n0 + col0]) = o;
    }
}

// ---------------------------------------------------------------------------
// Kernel 2: per-(window, head) attention + LePE + scatter.
// grid = (2048 windows, 12 heads), 128 threads.
// Gathers q/k/v rows via shifted-window token mapping, computes
// S = q k^T * scale + mask, softmax, O = P v, adds depthwise-3x3 LePE on v,
// scatters to output with reverse cyclic shift (same token mapping).
// ---------------------------------------------------------------------------
__global__ __launch_bounds__(128) void attn_kernel(const float* __restrict__ lepe_w,
                                                   const float* __restrict__ lepe_b,
                                                   float* __restrict__ out) {
    const int head = blockIdx.y;
    const int w    = blockIdx.x;
    const int b    = w >> 6;
    const int wi   = w & 63;
    const int wh   = wi >> 3;
    const int ww   = wi & 7;

    __shared__ float sq[49 * 32];
    __shared__ float sk[49 * 32];
    __shared__ float sv[49 * 32];
    __shared__ float S[49 * 52];       // row stride 52
    __shared__ int   stok[49];
    __shared__ int   sreg[49];
    __shared__ float swgt[32 * 9];

    const int tid = threadIdx.x;

    if (tid < 49) {
        int r = tid / 7, c = tid - (tid / 7) * 7;
        int ys = wh * 7 + r;
        int xs = ww * 7 + c;
        int y = ys + 3; if (y >= 56) y -= 56;   // reverse of roll(-3)
        int x = xs + 3; if (x >= 56) x -= 56;
        stok[tid] = b * 3136 + y * 56 + x;
        int rh = (ys < 49) ? 0 : ((ys < 53) ? 1 : 2);
        int rw = (xs < 49) ? 0 : ((xs < 53) ? 1 : 2);
        sreg[tid] = rh * 3 + rw;
    }
    for (int i = tid; i < 32 * 9; i += 128)
        swgt[i] = lepe_w[head * 32 * 9 + i];
    __syncthreads();

    // Gather q,k,v for this (window, head)
    for (int i = tid; i < 49 * 32; i += 128) {
        int n = i >> 5, j = i & 31;
        const float* base = g_qkv + (size_t)stok[n] * COUT + head * 32 + j;
        sq[i] = base[0];
        sk[i] = base[384];
        sv[i] = base[768];
    }
    __syncthreads();

    // S = q k^T * scale + mask
    const float scale = 0.17677669529663687f;   // 1/sqrt(32)
    for (int idx = tid; idx < 49 * 49; idx += 128) {
        int i = idx / 49;
        int m = idx - i * 49;
        const float4* qi = reinterpret_cast<const float4*>(sq + i * 32);
        const float4* km = reinterpret_cast<const float4*>(sk + m * 32);
        float s = 0.0f;
        #pragma unroll
        for (int j = 0; j < 8; j++) {
            float4 a = qi[j], kv = km[j];
            s += a.x * kv.x + a.y * kv.y + a.z * kv.z + a.w * kv.w;
        }
        s *= scale;
        if (sreg[i] != sreg[m]) s -= 100.0f;
        S[i * 52 + m] = s;
    }
    __syncthreads();

    // softmax over rows (49 rows, one per thread)
    if (tid < 49) {
        float* row = S + tid * 52;
        float mx = row[0];
        #pragma unroll 7
        for (int m = 1; m < 49; m++) mx = fmaxf(mx, row[m]);
        float sum = 0.0f;
        #pragma unroll 7
        for (int m = 0; m < 49; m++) {
            float e = __expf(row[m] - mx);
            row[m] = e;
            sum += e;
        }
        float inv = 1.0f / sum;
        #pragma unroll 7
        for (int m = 0; m < 49; m++) row[m] *= inv;
    }
    __syncthreads();

    // O = P v, plus LePE (depthwise 3x3 on v within the 7x7 window), scatter
    for (int idx = tid; idx < 49 * 32; idx += 128) {
        int n = idx >> 5, j = idx & 31;
        const float* Sn = S + n * 52;
        float o = 0.0f;
        #pragma unroll 7
        for (int m = 0; m < 49; m++) o = fmaf(Sn[m], sv[m * 32 + j], o);

        int r = n / 7, c = n - (n / 7) * 7;
        float lp = lepe_b[head * 32 + j];
        #pragma unroll
        for (int dy = 0; dy < 3; dy++) {
            int rr = r + dy - 1;
            if ((unsigned)rr < 7u) {
                #pragma unroll
                for (int dx = 0; dx < 3; dx++) {
                    int cc = c + dx - 1;
                    if ((unsigned)cc < 7u)
                        lp = fmaf(sv[(rr * 7 + cc) * 32 + j],
                                  swgt[j * 9 + dy * 3 + dx], lp);
                }
            }
        }
        out[(size_t)stok[n] * CIN + head * 32 + j] = o + lp;
    }
}

// ---------------------------------------------------------------------------
extern "C" void kernel_launch(void* const* d_in, const int* in_sizes, int n_in,
                              void* d_out, int out_size) {
    const float* X    = (const float*)d_in[0];   // query (32, 3136, 384)
    const float* Wqkv = (const float*)d_in[1];   // (1152, 384)
    const float* bqkv = (const float*)d_in[2];   // (1152,)
    const float* lw   = (const float*)d_in[3];   // (384,1,3,3)
    const float* lb   = (const float*)d_in[4];   // (384,)
    float* out = (float*)d_out;                  // (32, 3136, 384)

    qkv_gemm<<<dim3(TOK / BM, COUT / BN), 256>>>(X, Wqkv, bqkv);
    attn_kernel<<<dim3(NWIN, NHEAD), 128>>>(lw, lb, out);
}

// round 2
// speedup vs baseline: 2.3448x; 2.3448x over previous
#include <cuda_runtime.h>
#include <cuda_bf16.h>
#include <cstdint>

// Problem constants (fixed shapes)
#define TOK   100352          // B * H * W = 32 * 56 * 56
#define CIN   384
#define COUT  1152
#define NWIN  2048            // B * 64 windows
#define NHEAD 12

// Scratch
__device__ float g_qkv[(size_t)TOK * COUT];                 // 462 MB
__device__ __nv_bfloat16 g_Xh[(size_t)TOK * CIN];           // 77 MB
__device__ __nv_bfloat16 g_Xl[(size_t)TOK * CIN];           // 77 MB
__device__ __nv_bfloat16 g_Wh[(size_t)COUT * CIN];
__device__ __nv_bfloat16 g_Wl[(size_t)COUT * CIN];

// ---------------------------------------------------------------------------
// Kernel 0: split fp32 -> bf16 hi + bf16 lo (residual)
// ---------------------------------------------------------------------------
__global__ __launch_bounds__(256) void cvt_split(const float* __restrict__ src,
                                                 int n4, int which) {
    __nv_bfloat16* hi = which ? g_Wh : g_Xh;
    __nv_bfloat16* lo = which ? g_Wl : g_Xl;
    int i = blockIdx.x * blockDim.x + threadIdx.x;
    if (i >= n4) return;
    float4 v = reinterpret_cast<const float4*>(src)[i];
    float f[4] = {v.x, v.y, v.z, v.w};
    __nv_bfloat162 h2[2], l2[2];
    #pragma unroll
    for (int t = 0; t < 2; t++) {
        __nv_bfloat16 h0 = __float2bfloat16(f[2 * t]);
        __nv_bfloat16 h1 = __float2bfloat16(f[2 * t + 1]);
        __nv_bfloat16 l0 = __float2bfloat16(f[2 * t] - __bfloat162float(h0));
        __nv_bfloat16 l1 = __float2bfloat16(f[2 * t + 1] - __bfloat162float(h1));
        h2[t] = __nv_bfloat162(h0, h1);
        l2[t] = __nv_bfloat162(l0, l1);
    }
    reinterpret_cast<__nv_bfloat162*>(hi)[2 * i]     = h2[0];
    reinterpret_cast<__nv_bfloat162*>(hi)[2 * i + 1] = h2[1];
    reinterpret_cast<__nv_bfloat162*>(lo)[2 * i]     = l2[0];
    reinterpret_cast<__nv_bfloat162*>(lo)[2 * i + 1] = l2[1];
}

// ---------------------------------------------------------------------------
// Kernel 1: QKV GEMM  Y = X @ W^T + b  via bf16x3 mma.sync (fp32-accurate)
// BM=128, BN=128, BK=32, 256 threads (8 warps, 2x4), cp.async 2-stage.
// SMEM row layout: 128B per (row): chunks 0-3 = hi k0..31, 4-7 = lo k0..31,
// 16B chunk c stored at (c ^ (row&7)) -> conflict-free ldmatrix.
// ---------------------------------------------------------------------------
#define GBM 128
#define GBN 128
#define GBK 32
#define STAGE_BYTES 32768

#define LDSM4(R, addr) \
    asm volatile("ldmatrix.sync.aligned.m8n8.x4.shared.b16 {%0,%1,%2,%3}, [%4];" \
        : "=r"((R)[0]), "=r"((R)[1]), "=r"((R)[2]), "=r"((R)[3]) : "r"(addr))
#define LDSM2(R, addr) \
    asm volatile("ldmatrix.sync.aligned.m8n8.x2.shared.b16 {%0,%1}, [%2];" \
        : "=r"((R)[0]), "=r"((R)[1]) : "r"(addr))
#define MMA16816(C, A, B) \
    asm volatile("mma.sync.aligned.m16n8k16.row.col.f32.bf16.bf16.f32 " \
        "{%0,%1,%2,%3}, {%4,%5,%6,%7}, {%8,%9}, {%0,%1,%2,%3};" \
        : "+f"((C)[0]), "+f"((C)[1]), "+f"((C)[2]), "+f"((C)[3]) \
        : "r"((A)[0]), "r"((A)[1]), "r"((A)[2]), "r"((A)[3]), \
          "r"((B)[0]), "r"((B)[1]))
#define CPASYNC16(dst, src) \
    asm volatile("cp.async.cg.shared.global [%0], [%1], 16;" :: "r"(dst), "l"(src))

__global__ __launch_bounds__(256, 1) void qkv_gemm_mma(const float* __restrict__ bias) {
    extern __shared__ char sm_raw[];
    const uint32_t sbase = (uint32_t)__cvta_generic_to_shared(sm_raw);
    const int tid  = threadIdx.x;
    const int lane = tid & 31;
    const int warp = tid >> 5;
    const int n0 = blockIdx.x * GBN;
    const int m0 = blockIdx.y * GBM;
    const int wm = (warp >> 2) * 64;
    const int wn = (warp & 3) * 32;

    float acc[4][4][4];
    #pragma unroll
    for (int a = 0; a < 4; a++)
        #pragma unroll
        for (int b = 0; b < 4; b++)
            #pragma unroll
            for (int c = 0; c < 4; c++) acc[a][b][c] = 0.0f;

    auto load_stage = [&](int st, int k0) {
        uint32_t abase = sbase + st * STAGE_BYTES;
        uint32_t bbase = abase + 16384;
        int q0 = tid * 4;
        #pragma unroll
        for (int u = 0; u < 4; u++) {
            int q = q0 + u;
            int row = q >> 3, ch = q & 7;
            uint32_t soff = row * 128 + ((ch ^ (row & 7)) << 4);
            const __nv_bfloat16* sa = (ch < 4)
                ? (g_Xh + (size_t)(m0 + row) * CIN + k0 + ch * 8)
                : (g_Xl + (size_t)(m0 + row) * CIN + k0 + (ch - 4) * 8);
            CPASYNC16(abase + soff, sa);
            const __nv_bfloat16* sb = (ch < 4)
                ? (g_Wh + (size_t)(n0 + row) * CIN + k0 + ch * 8)
                : (g_Wl + (size_t)(n0 + row) * CIN + k0 + (ch - 4) * 8);
            CPASYNC16(bbase + soff, sb);
        }
        asm volatile("cp.async.commit_group;");
    };

    load_stage(0, 0);
    const int NIT = CIN / GBK;   // 12
    for (int it = 0; it < NIT; it++) {
        if (it + 1 < NIT) {
            load_stage((it + 1) & 1, (it + 1) * GBK);
            asm volatile("cp.async.wait_group 1;");
        } else {
            asm volatile("cp.async.wait_group 0;");
        }
        __syncthreads();

        uint32_t abase = sbase + (it & 1) * STAGE_BYTES;
        uint32_t bbase = abase + 16384;

        #pragma unroll
        for (int kk = 0; kk < 2; kk++) {
            uint32_t Ah[4][4], Al[4][4], Bh[4][2], Bl[4][2];
            int arow_in = (lane & 7) + ((lane >> 3) & 1) * 8;
            int acol    = lane >> 4;     // 0/1 -> k chunk within k16
            #pragma unroll
            for (int mt = 0; mt < 4; mt++) {
                int row = wm + mt * 16 + arow_in;
                int chh = kk * 2 + acol;
                LDSM4(Ah[mt], abase + row * 128 + ((chh ^ (row & 7)) << 4));
                int chl = chh + 4;
                LDSM4(Al[mt], abase + row * 128 + ((chl ^ (row & 7)) << 4));
            }
            int lb = lane & 15;
            int brow_in = lb & 7;
            int bcol    = lb >> 3;
            #pragma unroll
            for (int nt = 0; nt < 4; nt++) {
                int row = wn + nt * 8 + brow_in;
                int chh = kk * 2 + bcol;
                LDSM2(Bh[nt], bbase + row * 128 + ((chh ^ (row & 7)) << 4));
                int chl = chh + 4;
                LDSM2(Bl[nt], bbase + row * 128 + ((chl ^ (row & 7)) << 4));
            }
            // three compensated passes: hh, hl, lh (pass-major for ILP)
            #pragma unroll
            for (int mt = 0; mt < 4; mt++)
                #pragma unroll
                for (int nt = 0; nt < 4; nt++)
                    MMA16816(acc[mt][nt], Ah[mt], Bh[nt]);
            #pragma unroll
            for (int mt = 0; mt < 4; mt++)
                #pragma unroll
                for (int nt = 0; nt < 4; nt++)
                    MMA16816(acc[mt][nt], Ah[mt], Bl[nt]);
            #pragma unroll
            for (int mt = 0; mt < 4; mt++)
                #pragma unroll
                for (int nt = 0; nt < 4; nt++)
                    MMA16816(acc[mt][nt], Al[mt], Bh[nt]);
        }
        __syncthreads();
    }

    // epilogue: add bias, store fp32
    #pragma unroll
    for (int mt = 0; mt < 4; mt++) {
        #pragma unroll
        for (int nt = 0; nt < 4; nt++) {
            int gm = m0 + wm + mt * 16 + (lane >> 2);
            int gn = n0 + wn + nt * 8 + (lane & 3) * 2;
            float b0 = __ldg(bias + gn);
            float b1 = __ldg(bias + gn + 1);
            float2 v0 = {acc[mt][nt][0] + b0, acc[mt][nt][1] + b1};
            float2 v1 = {acc[mt][nt][2] + b0, acc[mt][nt][3] + b1};
            *reinterpret_cast<float2*>(&g_qkv[(size_t)gm * COUT + gn]) = v0;
            *reinterpret_cast<float2*>(&g_qkv[(size_t)(gm + 8) * COUT + gn]) = v1;
        }
    }
}

// ---------------------------------------------------------------------------
// Kernel 2: per-(window, head) attention + LePE + scatter.
// Stride-33 q/k/v rows (conflict-free for m-varying LDS), 4x4 register tiles.
// ---------------------------------------------------------------------------
__global__ __launch_bounds__(128) void attn_kernel(const float* __restrict__ lepe_w,
                                                   const float* __restrict__ lepe_b,
                                                   float* __restrict__ out) {
    const int head = blockIdx.y;
    const int w    = blockIdx.x;
    const int b    = w >> 6;
    const int wi   = w & 63;
    const int wh   = wi >> 3;
    const int ww   = wi & 7;

    __shared__ float sq[49 * 33];
    __shared__ float sk[49 * 33];
    __shared__ float sv[49 * 33];
    __shared__ float S[49 * 52];
    __shared__ int   stok[49];
    __shared__ int   sreg[49];
    __shared__ float swgt[32 * 9];

    const int tid = threadIdx.x;

    if (tid < 49) {
        int r = tid / 7, c = tid - (tid / 7) * 7;
        int ys = wh * 7 + r;
        int xs = ww * 7 + c;
        int y = ys + 3; if (y >= 56) y -= 56;
        int x = xs + 3; if (x >= 56) x -= 56;
        stok[tid] = b * 3136 + y * 56 + x;
        int rh = (ys < 49) ? 0 : ((ys < 53) ? 1 : 2);
        int rw = (xs < 49) ? 0 : ((xs < 53) ? 1 : 2);
        sreg[tid] = rh * 3 + rw;
    }
    for (int i = tid; i < 32 * 9; i += 128)
        swgt[i] = lepe_w[head * 32 * 9 + i];
    __syncthreads();

    for (int i = tid; i < 49 * 32; i += 128) {
        int n = i >> 5, j = i & 31;
        const float* base = g_qkv + (size_t)stok[n] * COUT + head * 32 + j;
        sq[n * 33 + j] = base[0];
        sk[n * 33 + j] = base[CIN];
        sv[n * 33 + j] = base[2 * CIN];
    }
    __syncthreads();

    // S = q k^T * scale + mask  (4x4 register tiles; 13x13 tile grid)
    const float scale = 0.17677669529663687f;
    for (int job = tid; job < 169; job += 128) {
        int it = job / 13, mt = job - it * 13;
        int i0 = it * 4, m0 = mt * 4;
        int ir[4], mc[4];
        #pragma unroll
        for (int r = 0; r < 4; r++) {
            ir[r] = min(i0 + r, 48) * 33;
            mc[r] = min(m0 + r, 48) * 33;
        }
        float a[4][4] = {};
        #pragma unroll 8
        for (int j = 0; j < 32; j++) {
            float qv[4], kv[4];
            #pragma unroll
            for (int r = 0; r < 4; r++) qv[r] = sq[ir[r] + j];
            #pragma unroll
            for (int c = 0; c < 4; c++) kv[c] = sk[mc[c] + j];
            #pragma unroll
            for (int r = 0; r < 4; r++)
                #pragma unroll
                for (int c = 0; c < 4; c++)
                    a[r][c] = fmaf(qv[r], kv[c], a[r][c]);
        }
        #pragma unroll
        for (int r = 0; r < 4; r++)
            #pragma unroll
            for (int c = 0; c < 4; c++) {
                int ii = i0 + r, mm = m0 + c;
                if (ii < 49 && mm < 49) {
                    float s = a[r][c] * scale;
                    if (sreg[ii] != sreg[mm]) s -= 100.0f;
                    S[ii * 52 + mm] = s;
                }
            }
    }
    __syncthreads();

    if (tid < 49) {
        float* row = S + tid * 52;
        float mx = row[0];
        for (int m = 1; m < 49; m++) mx = fmaxf(mx, row[m]);
        float sum = 0.0f;
        for (int m = 0; m < 49; m++) {
            float e = __expf(row[m] - mx);
            row[m] = e;
            sum += e;
        }
        float inv = 1.0f / sum;
        for (int m = 0; m < 49; m++) row[m] *= inv;
    }
    __syncthreads();

    // O = P v  (4x4 tiles) + LePE + scatter
    for (int job = tid; job < 104; job += 128) {
        int nt = job >> 3, jt = job & 7;
        int n0 = nt * 4, j0 = jt * 4;
        int nr[4];
        #pragma unroll
        for (int r = 0; r < 4; r++) nr[r] = min(n0 + r, 48);
        float a[4][4] = {};
        for (int m = 0; m < 49; m++) {
            float vv[4], pp[4];
            #pragma unroll
            for (int c = 0; c < 4; c++) vv[c] = sv[m * 33 + j0 + c];
            #pragma unroll
            for (int r = 0; r < 4; r++) pp[r] = S[nr[r] * 52 + m];
            #pragma unroll
            for (int r = 0; r < 4; r++)
                #pragma unroll
                for (int c = 0; c < 4; c++)
                    a[r][c] = fmaf(pp[r], vv[c], a[r][c]);
        }
        #pragma unroll
        for (int r = 0; r < 4; r++) {
            int n = n0 + r;
            if (n > 48) break;
            int rr = n / 7, cc = n - (n / 7) * 7;
            #pragma unroll
            for (int c = 0; c < 4; c++) {
                int j = j0 + c;
                float lp = __ldg(lepe_b + head * 32 + j);
                #pragma unroll
                for (int dy = 0; dy < 3; dy++) {
                    int y2 = rr + dy - 1;
                    if ((unsigned)y2 < 7u) {
                        #pragma unroll
                        for (int dx = 0; dx < 3; dx++) {
                            int x2 = cc + dx - 1;
                            if ((unsigned)x2 < 7u)
                                lp = fmaf(sv[(y2 * 7 + x2) * 33 + j],
                                          swgt[j * 9 + dy * 3 + dx], lp);
                        }
                    }
                }
                out[(size_t)stok[n] * CIN + head * 32 + j] = a[r][c] + lp;
            }
        }
    }
}

// ---------------------------------------------------------------------------
extern "C" void kernel_launch(void* const* d_in, const int* in_sizes, int n_in,
                              void* d_out, int out_size) {
    const float* X    = (const float*)d_in[0];   // (32, 3136, 384)
    const float* Wqkv = (const float*)d_in[1];   // (1152, 384)
    const float* bqkv = (const float*)d_in[2];   // (1152,)
    const float* lw   = (const float*)d_in[3];   // (384,1,3,3)
    const float* lb   = (const float*)d_in[4];   // (384,)
    float* out = (float*)d_out;

    cudaFuncSetAttribute(qkv_gemm_mma,
                         cudaFuncAttributeMaxDynamicSharedMemorySize, 2 * STAGE_BYTES);

    cvt_split<<<(TOK * CIN / 4) / 256, 256>>>(X, TOK * CIN / 4, 0);
    cvt_split<<<(COUT * CIN / 4) / 256, 256>>>(Wqkv, COUT * CIN / 4, 1);
    qkv_gemm_mma<<<dim3(COUT / GBN, TOK / GBM), 256, 2 * STAGE_BYTES>>>(bqkv);
    attn_kernel<<<dim3(NWIN, NHEAD), 128>>>(lw, lb, out);
}

// round 5
// speedup vs baseline: 2.7646x; 1.1790x over previous
#include <cuda_runtime.h>
#include <cuda_bf16.h>
#include <cstdint>

// Problem constants (fixed shapes)
#define TOK   100352          // B * H * W = 32 * 56 * 56
#define CIN   384
#define COUT  1152
#define NWIN  2048            // B * 64 windows
#define NHEAD 12

// Scratch
__device__ float g_qkv[(size_t)TOK * COUT];                 // 462 MB
__device__ __nv_bfloat16 g_Xh[(size_t)TOK * CIN];
__device__ __nv_bfloat16 g_Xl[(size_t)TOK * CIN];
__device__ __nv_bfloat16 g_Wh[(size_t)COUT * CIN];
__device__ __nv_bfloat16 g_Wl[(size_t)COUT * CIN];

// ---------------------------------------------------------------------------
// Kernel 0: split fp32 -> bf16 hi + bf16 lo (residual)
// ---------------------------------------------------------------------------
__global__ __launch_bounds__(256) void cvt_split(const float* __restrict__ src,
                                                 int n4, int which) {
    __nv_bfloat16* hi = which ? g_Wh : g_Xh;
    __nv_bfloat16* lo = which ? g_Wl : g_Xl;
    int i = blockIdx.x * blockDim.x + threadIdx.x;
    if (i >= n4) return;
    float4 v = reinterpret_cast<const float4*>(src)[i];
    float f[4] = {v.x, v.y, v.z, v.w};
    __nv_bfloat162 h2[2], l2[2];
    #pragma unroll
    for (int t = 0; t < 2; t++) {
        __nv_bfloat16 h0 = __float2bfloat16(f[2 * t]);
        __nv_bfloat16 h1 = __float2bfloat16(f[2 * t + 1]);
        __nv_bfloat16 l0 = __float2bfloat16(f[2 * t] - __bfloat162float(h0));
        __nv_bfloat16 l1 = __float2bfloat16(f[2 * t + 1] - __bfloat162float(h1));
        h2[t] = __nv_bfloat162(h0, h1);
        l2[t] = __nv_bfloat162(l0, l1);
    }
    reinterpret_cast<__nv_bfloat162*>(hi)[2 * i]     = h2[0];
    reinterpret_cast<__nv_bfloat162*>(hi)[2 * i + 1] = h2[1];
    reinterpret_cast<__nv_bfloat162*>(lo)[2 * i]     = l2[0];
    reinterpret_cast<__nv_bfloat162*>(lo)[2 * i + 1] = l2[1];
}

// ---------------------------------------------------------------------------
// Kernel 1: QKV GEMM  Y = X @ W^T + b  via bf16x3 mma.sync (fp32-accurate)
// BM=128, BN=128, BK=32, 256 threads (8 warps, 2x4), cp.async 3-stage,
// 2 CTAs/SM. SMEM row: 128B (hi k0..31 chunks 0-3, lo chunks 4-7),
// 16B chunk c stored at (c ^ (row&7)) -> conflict-free ldmatrix.
// ---------------------------------------------------------------------------
#define GBM 128
#define GBN 128
#define GBK 32
#define STAGE_BYTES 32768
#define NIT 12                      // 384 / 32
#define SMEM_TOTAL_G (3 * STAGE_BYTES)

#define LDSM4(R, addr) \
    asm volatile("ldmatrix.sync.aligned.m8n8.x4.shared.b16 {%0,%1,%2,%3}, [%4];" \
        : "=r"((R)[0]), "=r"((R)[1]), "=r"((R)[2]), "=r"((R)[3]) : "r"(addr))
#define LDSM2(R, addr) \
    asm volatile("ldmatrix.sync.aligned.m8n8.x2.shared.b16 {%0,%1}, [%2];" \
        : "=r"((R)[0]), "=r"((R)[1]) : "r"(addr))
#define MMA16816(C, A, B) \
    asm volatile("mma.sync.aligned.m16n8k16.row.col.f32.bf16.bf16.f32 " \
        "{%0,%1,%2,%3}, {%4,%5,%6,%7}, {%8,%9}, {%0,%1,%2,%3};" \
        : "+f"((C)[0]), "+f"((C)[1]), "+f"((C)[2]), "+f"((C)[3]) \
        : "r"((A)[0]), "r"((A)[1]), "r"((A)[2]), "r"((A)[3]), \
          "r"((B)[0]), "r"((B)[1]))
#define CPASYNC16(dst, src) \
    asm volatile("cp.async.cg.shared.global [%0], [%1], 16;" :: "r"(dst), "l"(src))

__global__ __launch_bounds__(256, 2) void qkv_gemm_mma(const float* __restrict__ bias) {
    extern __shared__ char sm_raw[];
    const uint32_t sbase = (uint32_t)__cvta_generic_to_shared(sm_raw);
    const int tid  = threadIdx.x;
    const int lane = tid & 31;
    const int warp = tid >> 5;
    const int n0 = blockIdx.x * GBN;
    const int m0 = blockIdx.y * GBM;
    const int wm = (warp >> 2) * 64;
    const int wn = (warp & 3) * 32;

    float acc[4][4][4];
    #pragma unroll
    for (int a = 0; a < 4; a++)
        #pragma unroll
        for (int b = 0; b < 4; b++)
            #pragma unroll
            for (int c = 0; c < 4; c++) acc[a][b][c] = 0.0f;

    auto load_stage = [&](int st) {
        const int k0 = st * GBK;
        uint32_t abase = sbase + (st % 3) * STAGE_BYTES;
        uint32_t bbase = abase + 16384;
        int q0 = tid * 4;
        #pragma unroll
        for (int u = 0; u < 4; u++) {
            int q = q0 + u;
            int row = q >> 3, ch = q & 7;
            uint32_t soff = row * 128 + ((ch ^ (row & 7)) << 4);
            const __nv_bfloat16* sa = (ch < 4)
                ? (g_Xh + (size_t)(m0 + row) * CIN + k0 + ch * 8)
                : (g_Xl + (size_t)(m0 + row) * CIN + k0 + (ch - 4) * 8);
            CPASYNC16(abase + soff, sa);
            const __nv_bfloat16* sb = (ch < 4)
                ? (g_Wh + (size_t)(n0 + row) * CIN + k0 + ch * 8)
                : (g_Wl + (size_t)(n0 + row) * CIN + k0 + (ch - 4) * 8);
            CPASYNC16(bbase + soff, sb);
        }
        asm volatile("cp.async.commit_group;");
    };

    load_stage(0);
    load_stage(1);

    #pragma unroll 1
    for (int it = 0; it < NIT; it++) {
        if (it + 1 < NIT) asm volatile("cp.async.wait_group 1;");
        else              asm volatile("cp.async.wait_group 0;");
        __syncthreads();
        if (it + 2 < NIT) load_stage(it + 2);

        uint32_t abase = sbase + (it % 3) * STAGE_BYTES;
        uint32_t bbase = abase + 16384;

        #pragma unroll
        for (int kk = 0; kk < 2; kk++) {
            uint32_t Ah[4][4], Al[4][4], Bh[4][2], Bl[4][2];
            int arow_in = (lane & 7) + ((lane >> 3) & 1) * 8;
            int acol    = lane >> 4;
            #pragma unroll
            for (int mt = 0; mt < 4; mt++) {
                int row = wm + mt * 16 + arow_in;
                int chh = kk * 2 + acol;
                LDSM4(Ah[mt], abase + row * 128 + ((chh ^ (row & 7)) << 4));
                int chl = chh + 4;
                LDSM4(Al[mt], abase + row * 128 + ((chl ^ (row & 7)) << 4));
            }
            int lb = lane & 15;
            int brow_in = lb & 7;
            int bcol    = lb >> 3;
            #pragma unroll
            for (int nt = 0; nt < 4; nt++) {
                int row = wn + nt * 8 + brow_in;
                int chh = kk * 2 + bcol;
                LDSM2(Bh[nt], bbase + row * 128 + ((chh ^ (row & 7)) << 4));
                int chl = chh + 4;
                LDSM2(Bl[nt], bbase + row * 128 + ((chl ^ (row & 7)) << 4));
            }
            #pragma unroll
            for (int mt = 0; mt < 4; mt++)
                #pragma unroll
                for (int nt = 0; nt < 4; nt++)
                    MMA16816(acc[mt][nt], Ah[mt], Bh[nt]);
            #pragma unroll
            for (int mt = 0; mt < 4; mt++)
                #pragma unroll
                for (int nt = 0; nt < 4; nt++)
                    MMA16816(acc[mt][nt], Ah[mt], Bl[nt]);
            #pragma unroll
            for (int mt = 0; mt < 4; mt++)
                #pragma unroll
                for (int nt = 0; nt < 4; nt++)
                    MMA16816(acc[mt][nt], Al[mt], Bh[nt]);
        }
    }

    // epilogue: add bias, store fp32
    #pragma unroll
    for (int mt = 0; mt < 4; mt++) {
        #pragma unroll
        for (int nt = 0; nt < 4; nt++) {
            int gm = m0 + wm + mt * 16 + (lane >> 2);
            int gn = n0 + wn + nt * 8 + (lane & 3) * 2;
            float b0 = __ldg(bias + gn);
            float b1 = __ldg(bias + gn + 1);
            float2 v0 = {acc[mt][nt][0] + b0, acc[mt][nt][1] + b1};
            float2 v1 = {acc[mt][nt][2] + b0, acc[mt][nt][3] + b1};
            *reinterpret_cast<float2*>(&g_qkv[(size_t)gm * COUT + gn]) = v0;
            *reinterpret_cast<float2*>(&g_qkv[(size_t)(gm + 8) * COUT + gn]) = v1;
        }
    }
}

// ---------------------------------------------------------------------------
// Kernel 2: attention + LePE + scatter, broadcast-friendly thread mapping.
// All float4-viewed shared arrays are alignas(16) (the R4 trap).
// ---------------------------------------------------------------------------
__global__ __launch_bounds__(128) void attn_kernel(const float* __restrict__ lepe_w,
                                                   const float* __restrict__ lepe_b,
                                                   float* __restrict__ out) {
    const int head = blockIdx.y;
    const int w    = blockIdx.x;
    const int b    = w >> 6;
    const int wi   = w & 63;
    const int wh   = wi >> 3;
    const int ww   = wi & 7;

    __shared__ alignas(16) float sq[49 * 36];
    __shared__ alignas(16) float sk[49 * 36];
    __shared__ alignas(16) float sv[49 * 36];
    __shared__ alignas(16) float S[49 * 53];
    __shared__ alignas(16) float swgt[9 * 32];     // [tap][j]
    __shared__ int   stok[49];
    __shared__ int   sreg[49];

    const int tid = threadIdx.x;

    if (tid < 49) {
        int r = tid / 7, c = tid - (tid / 7) * 7;
        int ys = wh * 7 + r;
        int xs = ww * 7 + c;
        int y = ys + 3; if (y >= 56) y -= 56;
        int x = xs + 3; if (x >= 56) x -= 56;
        stok[tid] = b * 3136 + y * 56 + x;
        int rh = (ys < 49) ? 0 : ((ys < 53) ? 1 : 2);
        int rw = (xs < 49) ? 0 : ((xs < 53) ? 1 : 2);
        sreg[tid] = rh * 3 + rw;
    }
    for (int i = tid; i < 9 * 32; i += 128) {
        int tap = i >> 5, j = i & 31;
        swgt[i] = lepe_w[head * 288 + j * 9 + tap];
    }
    __syncthreads();

    // Gather q,k,v (vectorized)
    for (int i = tid; i < 49 * 8; i += 128) {
        int n = i >> 3, u = i & 7;
        const float4* base = reinterpret_cast<const float4*>(
            g_qkv + (size_t)stok[n] * COUT + head * 32) + u;
        reinterpret_cast<float4*>(sq + n * 36)[u] = base[0];
        reinterpret_cast<float4*>(sk + n * 36)[u] = base[CIN / 4];
        reinterpret_cast<float4*>(sv + n * 36)[u] = base[2 * CIN / 4];
    }
    __syncthreads();

    // S = q k^T * scale + mask.  98 threads: i = tid mod 49, m-half = tid/49.
    const float scale = 0.17677669529663687f;
    if (tid < 98) {
        const int i    = (tid < 49) ? tid : tid - 49;
        const int half = (tid < 49) ? 0 : 1;
        const int mlo  = half ? 25 : 0;
        const int mhi  = half ? 49 : 25;
        float4 q[8];
        const float4* qr = reinterpret_cast<const float4*>(sq + i * 36);
        #pragma unroll
        for (int u = 0; u < 8; u++) q[u] = qr[u];
        const int regi = sreg[i];
        float* Srow = S + i * 53;
        for (int m = mlo; m < mhi; m++) {
            const float4* kr = reinterpret_cast<const float4*>(sk + m * 36);
            float a = 0.0f;
            #pragma unroll
            for (int u = 0; u < 8; u++) {
                float4 kv = kr[u];
                a = fmaf(q[u].x, kv.x, a);
                a = fmaf(q[u].y, kv.y, a);
                a = fmaf(q[u].z, kv.z, a);
                a = fmaf(q[u].w, kv.w, a);
            }
            a *= scale;
            if (regi != sreg[m]) a -= 100.0f;
            Srow[m] = a;
        }
    }
    __syncthreads();

    // softmax rows
    if (tid < 49) {
        float* row = S + tid * 53;
        float mx = row[0];
        for (int m = 1; m < 49; m++) mx = fmaxf(mx, row[m]);
        float sum = 0.0f;
        for (int m = 0; m < 49; m++) {
            float e = __expf(row[m] - mx);
            row[m] = e;
            sum += e;
        }
        float inv = 1.0f / sum;
        for (int m = 0; m < 49; m++) row[m] *= inv;
    }
    __syncthreads();

    // O = P v + LePE; 98 threads: n = tid mod 49, j-half = tid/49 (16 ch each)
    if (tid < 98) {
        const int n  = (tid < 49) ? tid : tid - 49;
        const int j0 = (tid < 49) ? 0 : 16;
        float4 acc[4] = {};
        const float* Srow = S + n * 53;
        for (int m = 0; m < 49; m++) {
            float p = Srow[m];
            const float4* vr = reinterpret_cast<const float4*>(sv + m * 36 + j0);
            #pragma unroll
            for (int c = 0; c < 4; c++) {
                float4 vv = vr[c];
                acc[c].x = fmaf(p, vv.x, acc[c].x);
                acc[c].y = fmaf(p, vv.y, acc[c].y);
                acc[c].z = fmaf(p, vv.z, acc[c].z);
                acc[c].w = fmaf(p, vv.w, acc[c].w);
            }
        }
        // LePE
        float4 lp[4];
        #pragma unroll
        for (int c = 0; c < 4; c++)
            lp[c] = __ldg(reinterpret_cast<const float4*>(lepe_b + head * 32 + j0) + c);
        const int rr = n / 7, cc = n - (n / 7) * 7;
        #pragma unroll
        for (int dy = 0; dy < 3; dy++) {
            int y2 = rr + dy - 1;
            if ((unsigned)y2 >= 7u) continue;
            #pragma unroll
            for (int dx = 0; dx < 3; dx++) {
                int x2 = cc + dx - 1;
                if ((unsigned)x2 >= 7u) continue;
                const int tap = dy * 3 + dx;
                const float4* vr = reinterpret_cast<const float4*>(
                    sv + (y2 * 7 + x2) * 36 + j0);
                const float4* wt = reinterpret_cast<const float4*>(swgt + tap * 32 + j0);
                #pragma unroll
                for (int c = 0; c < 4; c++) {
                    float4 vv = vr[c], ww2 = wt[c];
                    lp[c].x = fmaf(vv.x, ww2.x, lp[c].x);
                    lp[c].y = fmaf(vv.y, ww2.y, lp[c].y);
                    lp[c].z = fmaf(vv.z, ww2.z, lp[c].z);
                    lp[c].w = fmaf(vv.w, ww2.w, lp[c].w);
                }
            }
        }
        float* dst = out + (size_t)stok[n] * CIN + head * 32 + j0;
        #pragma unroll
        for (int c = 0; c < 4; c++) {
            float4 o;
            o.x = acc[c].x + lp[c].x;
            o.y = acc[c].y + lp[c].y;
            o.z = acc[c].z + lp[c].z;
            o.w = acc[c].w + lp[c].w;
            reinterpret_cast<float4*>(dst)[c] = o;
        }
    }
}

// ---------------------------------------------------------------------------
extern "C" void kernel_launch(void* const* d_in, const int* in_sizes, int n_in,
                              void* d_out, int out_size) {
    const float* X    = (const float*)d_in[0];   // (32, 3136, 384)
    const float* Wqkv = (const float*)d_in[1];   // (1152, 384)
    const float* bqkv = (const float*)d_in[2];   // (1152,)
    const float* lw   = (const float*)d_in[3];   // (384,1,3,3)
    const float* lb   = (const float*)d_in[4];   // (384,)
    float* out = (float*)d_out;

    cudaFuncSetAttribute(qkv_gemm_mma,
                         cudaFuncAttributeMaxDynamicSharedMemorySize, SMEM_TOTAL_G);

    cvt_split<<<(TOK * CIN / 4) / 256, 256>>>(X, TOK * CIN / 4, 0);
    cvt_split<<<(COUT * CIN / 4) / 256, 256>>>(Wqkv, COUT * CIN / 4, 1);
    qkv_gemm_mma<<<dim3(COUT / GBN, TOK / GBM), 256, SMEM_TOTAL_G>>>(bqkv);
    attn_kernel<<<dim3(NWIN, NHEAD), 128>>>(lw, lb, out);
}

// round 6
// speedup vs baseline: 4.9159x; 1.7782x over previous
#include <cuda_runtime.h>
#include <cuda_bf16.h>
#include <cuda_fp16.h>
#include <cstdint>

// Problem constants (fixed shapes)
#define TOK   100352          // B * H * W = 32 * 56 * 56
#define CIN   384
#define COUT  1152
#define NWIN  2048            // B * 64 windows
#define NHEAD 12

// Scratch
__device__ float g_qkv[(size_t)TOK * COUT];                 // 462 MB
__device__ __half g_Xh[(size_t)TOK * CIN];                  // 77 MB
__device__ __half g_Wh[(size_t)COUT * CIN];

// ---------------------------------------------------------------------------
// Kernel 0: fp32 -> fp16
// ---------------------------------------------------------------------------
__global__ __launch_bounds__(256) void cvt_f16(const float* __restrict__ src,
                                               int n4, int which) {
    __half* dst = which ? g_Wh : g_Xh;
    int i = blockIdx.x * blockDim.x + threadIdx.x;
    if (i >= n4) return;
    float4 v = reinterpret_cast<const float4*>(src)[i];
    __half2 h0 = __floats2half2_rn(v.x, v.y);
    __half2 h1 = __floats2half2_rn(v.z, v.w);
    reinterpret_cast<__half2*>(dst)[2 * i]     = h0;
    reinterpret_cast<__half2*>(dst)[2 * i + 1] = h1;
}

// ---------------------------------------------------------------------------
// Kernel 1: QKV GEMM  Y = X @ W^T + b  via fp16 mma.sync, fp32 accum.
// BM=128, BN=128, BK=32, 256 threads (8 warps, 2x4), cp.async 3-stage.
// Tile rows are 64B (32 fp16); two rows share a 128B line. Chunk c (16B) of
// row r lives at (r>>1)*128 + (((r&1)*4+c) ^ ((r>>1)&7))*16 -> the 8 rows of
// any ldmatrix 8x8 read hit 8 distinct 16B bank groups.
// ---------------------------------------------------------------------------
#define GBM 128
#define GBN 128
#define GBK 32
#define STAGE_BYTES 16384           // A 8KB + B 8KB
#define NIT 12                      // 384 / 32
#define SMEM_TOTAL_G (3 * STAGE_BYTES)

__device__ __forceinline__ uint32_t tile_off(int r, int c) {
    return (uint32_t)((r >> 1) * 128 + ((((r & 1) * 4 + c) ^ ((r >> 1) & 7)) << 4));
}

#define LDSM4(R, addr) \
    asm volatile("ldmatrix.sync.aligned.m8n8.x4.shared.b16 {%0,%1,%2,%3}, [%4];" \
        : "=r"((R)[0]), "=r"((R)[1]), "=r"((R)[2]), "=r"((R)[3]) : "r"(addr))
#define LDSM2(R, addr) \
    asm volatile("ldmatrix.sync.aligned.m8n8.x2.shared.b16 {%0,%1}, [%2];" \
        : "=r"((R)[0]), "=r"((R)[1]) : "r"(addr))
#define MMA16816F16(C, A, B) \
    asm volatile("mma.sync.aligned.m16n8k16.row.col.f32.f16.f16.f32 " \
        "{%0,%1,%2,%3}, {%4,%5,%6,%7}, {%8,%9}, {%0,%1,%2,%3};" \
        : "+f"((C)[0]), "+f"((C)[1]), "+f"((C)[2]), "+f"((C)[3]) \
        : "r"((A)[0]), "r"((A)[1]), "r"((A)[2]), "r"((A)[3]), \
          "r"((B)[0]), "r"((B)[1]))
#define CPASYNC16(dst, src) \
    asm volatile("cp.async.cg.shared.global [%0], [%1], 16;" :: "r"(dst), "l"(src))

__global__ __launch_bounds__(256, 2) void qkv_gemm_mma(const float* __restrict__ bias) {
    extern __shared__ char sm_raw[];
    const uint32_t sbase = (uint32_t)__cvta_generic_to_shared(sm_raw);
    const int tid  = threadIdx.x;
    const int lane = tid & 31;
    const int warp = tid >> 5;
    const int n0 = blockIdx.x * GBN;
    const int m0 = blockIdx.y * GBM;
    const int wm = (warp >> 2) * 64;
    const int wn = (warp & 3) * 32;

    float acc[4][4][4];
    #pragma unroll
    for (int a = 0; a < 4; a++)
        #pragma unroll
        for (int b = 0; b < 4; b++)
            #pragma unroll
            for (int c = 0; c < 4; c++) acc[a][b][c] = 0.0f;

    auto load_stage = [&](int st) {
        const int k0 = st * GBK;
        uint32_t abase = sbase + (st % 3) * STAGE_BYTES;
        uint32_t bbase = abase + 8192;
        #pragma unroll
        for (int u = 0; u < 2; u++) {
            int q = tid * 2 + u;
            int r = q >> 2, c = q & 3;
            uint32_t soff = tile_off(r, c);
            CPASYNC16(abase + soff, g_Xh + (size_t)(m0 + r) * CIN + k0 + c * 8);
            CPASYNC16(bbase + soff, g_Wh + (size_t)(n0 + r) * CIN + k0 + c * 8);
        }
        asm volatile("cp.async.commit_group;");
    };

    load_stage(0);
    load_stage(1);

    #pragma unroll 1
    for (int it = 0; it < NIT; it++) {
        if (it + 1 < NIT) asm volatile("cp.async.wait_group 1;");
        else              asm volatile("cp.async.wait_group 0;");
        __syncthreads();
        if (it + 2 < NIT) load_stage(it + 2);

        uint32_t abase = sbase + (it % 3) * STAGE_BYTES;
        uint32_t bbase = abase + 8192;

        #pragma unroll
        for (int kk = 0; kk < 2; kk++) {
            uint32_t Ah[4][4], Bh[4][2];
            int arow_in = (lane & 7) + ((lane >> 3) & 1) * 8;
            int acol    = lane >> 4;
            #pragma unroll
            for (int mt = 0; mt < 4; mt++) {
                int row = wm + mt * 16 + arow_in;
                LDSM4(Ah[mt], abase + tile_off(row, kk * 2 + acol));
            }
            int lb = lane & 15;
            int brow_in = lb & 7;
            int bcol    = lb >> 3;
            #pragma unroll
            for (int nt = 0; nt < 4; nt++) {
                int row = wn + nt * 8 + brow_in;
                LDSM2(Bh[nt], bbase + tile_off(row, kk * 2 + bcol));
            }
            #pragma unroll
            for (int mt = 0; mt < 4; mt++)
                #pragma unroll
                for (int nt = 0; nt < 4; nt++)
                    MMA16816F16(acc[mt][nt], Ah[mt], Bh[nt]);
        }
    }

    // epilogue: add bias, store fp32
    #pragma unroll
    for (int mt = 0; mt < 4; mt++) {
        #pragma unroll
        for (int nt = 0; nt < 4; nt++) {
            int gm = m0 + wm + mt * 16 + (lane >> 2);
            int gn = n0 + wn + nt * 8 + (lane & 3) * 2;
            float b0 = __ldg(bias + gn);
            float b1 = __ldg(bias + gn + 1);
            float2 v0 = {acc[mt][nt][0] + b0, acc[mt][nt][1] + b1};
            float2 v1 = {acc[mt][nt][2] + b0, acc[mt][nt][3] + b1};
            *reinterpret_cast<float2*>(&g_qkv[(size_t)gm * COUT + gn]) = v0;
            *reinterpret_cast<float2*>(&g_qkv[(size_t)(gm + 8) * COUT + gn]) = v1;
        }
    }
}

// ---------------------------------------------------------------------------
// Kernel 2: attention + LePE + scatter.
// Warp-aligned halves (half = tid>>6): every warp has uniform control flow
// and warp-uniform (broadcast) k/v smem reads. q lives in registers (gmem
// loads), so no sq array -> ~25.5KB smem -> 8 CTAs/SM.
// ---------------------------------------------------------------------------
__global__ __launch_bounds__(128, 8) void attn_kernel(const float* __restrict__ lepe_w,
                                                      const float* __restrict__ lepe_b,
                                                      float* __restrict__ out) {
    const int head = blockIdx.y;
    const int w    = blockIdx.x;
    const int b    = w >> 6;
    const int wi   = w & 63;
    const int wh   = wi >> 3;
    const int ww   = wi & 7;

    __shared__ alignas(16) float sk[49 * 36];
    __shared__ alignas(16) float sv[49 * 36];
    __shared__ alignas(16) float S[49 * 53];
    __shared__ alignas(16) float swgt[9 * 32];     // [tap][j]
    __shared__ int   stok[49];
    __shared__ int   sreg[49];

    const int tid = threadIdx.x;

    if (tid < 49) {
        int r = tid / 7, c = tid - (tid / 7) * 7;
        int ys = wh * 7 + r;
        int xs = ww * 7 + c;
        int y = ys + 3; if (y >= 56) y -= 56;
        int x = xs + 3; if (x >= 56) x -= 56;
        stok[tid] = b * 3136 + y * 56 + x;
        int rh = (ys < 49) ? 0 : ((ys < 53) ? 1 : 2);
        int rw = (xs < 49) ? 0 : ((xs < 53) ? 1 : 2);
        sreg[tid] = rh * 3 + rw;
    }
    for (int i = tid; i < 9 * 32; i += 128) {
        int tap = i >> 5, j = i & 31;
        swgt[i] = lepe_w[head * 288 + j * 9 + tap];
    }
    __syncthreads();

    // Gather k,v (vectorized)
    for (int i = tid; i < 49 * 8; i += 128) {
        int n = i >> 3, u = i & 7;
        const float4* base = reinterpret_cast<const float4*>(
            g_qkv + (size_t)stok[n] * COUT + head * 32);
        reinterpret_cast<float4*>(sk + n * 36)[u] = base[96 + u];
        reinterpret_cast<float4*>(sv + n * 36)[u] = base[192 + u];
    }
    __syncthreads();

    // S = q k^T * scale + mask.  half = tid>>6 (warp-aligned), ii = tid&63.
    const float scale = 0.17677669529663687f;
    {
        const int half = tid >> 6;
        const int ii   = tid & 63;
        if (ii < 49) {
            const float4* qr = reinterpret_cast<const float4*>(
                g_qkv + (size_t)stok[ii] * COUT + head * 32);
            float4 q[8];
            #pragma unroll
            for (int u = 0; u < 8; u++) q[u] = __ldg(qr + u);
            const int regi = sreg[ii];
            const int mlo = half ? 25 : 0;
            const int mhi = half ? 49 : 25;
            float* Srow = S + ii * 53;
            for (int m = mlo; m < mhi; m++) {
                const float4* kr = reinterpret_cast<const float4*>(sk + m * 36);
                float a = 0.0f;
                #pragma unroll
                for (int u = 0; u < 8; u++) {
                    float4 kv = kr[u];
                    a = fmaf(q[u].x, kv.x, a);
                    a = fmaf(q[u].y, kv.y, a);
                    a = fmaf(q[u].z, kv.z, a);
                    a = fmaf(q[u].w, kv.w, a);
                }
                a *= scale;
                if (regi != sreg[m]) a -= 100.0f;
                Srow[m] = a;
            }
        }
    }
    __syncthreads();

    // softmax rows
    if (tid < 49) {
        float* row = S + tid * 53;
        float mx = row[0];
        for (int m = 1; m < 49; m++) mx = fmaxf(mx, row[m]);
        float sum = 0.0f;
        for (int m = 0; m < 49; m++) {
            float e = __expf(row[m] - mx);
            row[m] = e;
            sum += e;
        }
        float inv = 1.0f / sum;
        for (int m = 0; m < 49; m++) row[m] *= inv;
    }
    __syncthreads();

    // O = P v + LePE; half = tid>>6 -> j0 in {0,16}, n = tid&63.
    {
        const int half = tid >> 6;
        const int n    = tid & 63;
        if (n < 49) {
            const int j0 = half * 16;
            float4 acc[4] = {};
            const float* Srow = S + n * 53;
            for (int m = 0; m < 49; m++) {
                float p = Srow[m];
                const float4* vr = reinterpret_cast<const float4*>(sv + m * 36 + j0);
                #pragma unroll
                for (int c = 0; c < 4; c++) {
                    float4 vv = vr[c];
                    acc[c].x = fmaf(p, vv.x, acc[c].x);
                    acc[c].y = fmaf(p, vv.y, acc[c].y);
                    acc[c].z = fmaf(p, vv.z, acc[c].z);
                    acc[c].w = fmaf(p, vv.w, acc[c].w);
                }
            }
            // LePE
            float4 lp[4];
            #pragma unroll
            for (int c = 0; c < 4; c++)
                lp[c] = __ldg(reinterpret_cast<const float4*>(lepe_b + head * 32 + j0) + c);
            const int rr = n / 7, cc = n - (n / 7) * 7;
            #pragma unroll
            for (int dy = 0; dy < 3; dy++) {
                int y2 = rr + dy - 1;
                if ((unsigned)y2 >= 7u) continue;
                #pragma unroll
                for (int dx = 0; dx < 3; dx++) {
                    int x2 = cc + dx - 1;
                    if ((unsigned)x2 >= 7u) continue;
                    const int tap = dy * 3 + dx;
                    const float4* vr = reinterpret_cast<const float4*>(
                        sv + (y2 * 7 + x2) * 36 + j0);
                    const float4* wt = reinterpret_cast<const float4*>(swgt + tap * 32 + j0);
                    #pragma unroll
                    for (int c = 0; c < 4; c++) {
                        float4 vv = vr[c], ww2 = wt[c];
                        lp[c].x = fmaf(vv.x, ww2.x, lp[c].x);
                        lp[c].y = fmaf(vv.y, ww2.y, lp[c].y);
                        lp[c].z = fmaf(vv.z, ww2.z, lp[c].z);
                        lp[c].w = fmaf(vv.w, ww2.w, lp[c].w);
                    }
                }
            }
            float* dst = out + (size_t)stok[n] * CIN + head * 32 + j0;
            #pragma unroll
            for (int c = 0; c < 4; c++) {
                float4 o;
                o.x = acc[c].x + lp[c].x;
                o.y = acc[c].y + lp[c].y;
                o.z = acc[c].z + lp[c].z;
                o.w = acc[c].w + lp[c].w;
                reinterpret_cast<float4*>(dst)[c] = o;
            }
        }
    }
}

// ---------------------------------------------------------------------------
extern "C" void kernel_launch(void* const* d_in, const int* in_sizes, int n_in,
                              void* d_out, int out_size) {
    const float* X    = (const float*)d_in[0];   // (32, 3136, 384)
    const float* Wqkv = (const float*)d_in[1];   // (1152, 384)
    const float* bqkv = (const float*)d_in[2];   // (1152,)
    const float* lw   = (const float*)d_in[3];   // (384,1,3,3)
    const float* lb   = (const float*)d_in[4];   // (384,)
    float* out = (float*)d_out;

    cudaFuncSetAttribute(qkv_gemm_mma,
                         cudaFuncAttributeMaxDynamicSharedMemorySize, SMEM_TOTAL_G);

    cvt_f16<<<(TOK * CIN / 4) / 256, 256>>>(X, TOK * CIN / 4, 0);
    cvt_f16<<<(COUT * CIN / 4) / 256, 256>>>(Wqkv, COUT * CIN / 4, 1);
    qkv_gemm_mma<<<dim3(COUT / GBN, TOK / GBM), 256, SMEM_TOTAL_G>>>(bqkv);
    attn_kernel<<<dim3(NWIN, NHEAD), 128>>>(lw, lb, out);
}

// round 7
// speedup vs baseline: 5.3878x; 1.0960x over previous
#include <cuda_runtime.h>
#include <cuda_bf16.h>
#include <cuda_fp16.h>
#include <cstdint>

// Problem constants (fixed shapes)
#define TOK   100352          // B * H * W = 32 * 56 * 56
#define CIN   384
#define COUT  1152
#define NWIN  2048            // B * 64 windows
#define NHEAD 12

// Scratch
__device__ __half g_qkvh[(size_t)TOK * COUT];               // 231 MB (fp16)
__device__ __half g_Xh[(size_t)TOK * CIN];                  // 77 MB
__device__ __half g_Wh[(size_t)COUT * CIN];

// ---------------------------------------------------------------------------
// Kernel 0: fp32 -> fp16
// ---------------------------------------------------------------------------
__global__ __launch_bounds__(256) void cvt_f16(const float* __restrict__ src,
                                               int n4, int which) {
    __half* dst = which ? g_Wh : g_Xh;
    int i = blockIdx.x * blockDim.x + threadIdx.x;
    if (i >= n4) return;
    float4 v = reinterpret_cast<const float4*>(src)[i];
    __half2 h0 = __floats2half2_rn(v.x, v.y);
    __half2 h1 = __floats2half2_rn(v.z, v.w);
    reinterpret_cast<__half2*>(dst)[2 * i]     = h0;
    reinterpret_cast<__half2*>(dst)[2 * i + 1] = h1;
}

// ---------------------------------------------------------------------------
// Kernel 1: QKV GEMM  Y = X @ W^T + b  via fp16 mma.sync, fp32 accum,
// fp16 output. BM=128, BN=128, BK=32, 256 threads, cp.async 3-stage.
// ---------------------------------------------------------------------------
#define GBM 128
#define GBN 128
#define GBK 32
#define STAGE_BYTES 16384           // A 8KB + B 8KB
#define NIT 12                      // 384 / 32
#define SMEM_TOTAL_G (3 * STAGE_BYTES)

__device__ __forceinline__ uint32_t tile_off(int r, int c) {
    return (uint32_t)((r >> 1) * 128 + ((((r & 1) * 4 + c) ^ ((r >> 1) & 7)) << 4));
}

#define LDSM4(R, addr) \
    asm volatile("ldmatrix.sync.aligned.m8n8.x4.shared.b16 {%0,%1,%2,%3}, [%4];" \
        : "=r"((R)[0]), "=r"((R)[1]), "=r"((R)[2]), "=r"((R)[3]) : "r"(addr))
#define LDSM2(R, addr) \
    asm volatile("ldmatrix.sync.aligned.m8n8.x2.shared.b16 {%0,%1}, [%2];" \
        : "=r"((R)[0]), "=r"((R)[1]) : "r"(addr))
#define MMA16816F16(C, A, B) \
    asm volatile("mma.sync.aligned.m16n8k16.row.col.f32.f16.f16.f32 " \
        "{%0,%1,%2,%3}, {%4,%5,%6,%7}, {%8,%9}, {%0,%1,%2,%3};" \
        : "+f"((C)[0]), "+f"((C)[1]), "+f"((C)[2]), "+f"((C)[3]) \
        : "r"((A)[0]), "r"((A)[1]), "r"((A)[2]), "r"((A)[3]), \
          "r"((B)[0]), "r"((B)[1]))
#define CPASYNC16(dst, src) \
    asm volatile("cp.async.cg.shared.global [%0], [%1], 16;" :: "r"(dst), "l"(src))

__global__ __launch_bounds__(256, 2) void qkv_gemm_mma(const float* __restrict__ bias) {
    extern __shared__ char sm_raw[];
    const uint32_t sbase = (uint32_t)__cvta_generic_to_shared(sm_raw);
    const int tid  = threadIdx.x;
    const int lane = tid & 31;
    const int warp = tid >> 5;
    const int n0 = blockIdx.x * GBN;
    const int m0 = blockIdx.y * GBM;
    const int wm = (warp >> 2) * 64;
    const int wn = (warp & 3) * 32;

    float acc[4][4][4];
    #pragma unroll
    for (int a = 0; a < 4; a++)
        #pragma unroll
        for (int b = 0; b < 4; b++)
            #pragma unroll
            for (int c = 0; c < 4; c++) acc[a][b][c] = 0.0f;

    auto load_stage = [&](int st) {
        const int k0 = st * GBK;
        uint32_t abase = sbase + (st % 3) * STAGE_BYTES;
        uint32_t bbase = abase + 8192;
        #pragma unroll
        for (int u = 0; u < 2; u++) {
            int q = tid * 2 + u;
            int r = q >> 2, c = q & 3;
            uint32_t soff = tile_off(r, c);
            CPASYNC16(abase + soff, g_Xh + (size_t)(m0 + r) * CIN + k0 + c * 8);
            CPASYNC16(bbase + soff, g_Wh + (size_t)(n0 + r) * CIN + k0 + c * 8);
        }
        asm volatile("cp.async.commit_group;");
    };

    load_stage(0);
    load_stage(1);

    #pragma unroll 1
    for (int it = 0; it < NIT; it++) {
        if (it + 1 < NIT) asm volatile("cp.async.wait_group 1;");
        else              asm volatile("cp.async.wait_group 0;");
        __syncthreads();
        if (it + 2 < NIT) load_stage(it + 2);

        uint32_t abase = sbase + (it % 3) * STAGE_BYTES;
        uint32_t bbase = abase + 8192;

        #pragma unroll
        for (int kk = 0; kk < 2; kk++) {
            uint32_t Ah[4][4], Bh[4][2];
            int arow_in = (lane & 7) + ((lane >> 3) & 1) * 8;
            int acol    = lane >> 4;
            #pragma unroll
            for (int mt = 0; mt < 4; mt++) {
                int row = wm + mt * 16 + arow_in;
                LDSM4(Ah[mt], abase + tile_off(row, kk * 2 + acol));
            }
            int lb = lane & 15;
            int brow_in = lb & 7;
            int bcol    = lb >> 3;
            #pragma unroll
            for (int nt = 0; nt < 4; nt++) {
                int row = wn + nt * 8 + brow_in;
                LDSM2(Bh[nt], bbase + tile_off(row, kk * 2 + bcol));
            }
            #pragma unroll
            for (int mt = 0; mt < 4; mt++)
                #pragma unroll
                for (int nt = 0; nt < 4; nt++)
                    MMA16816F16(acc[mt][nt], Ah[mt], Bh[nt]);
        }
    }

    // epilogue: add bias, store fp16
    #pragma unroll
    for (int mt = 0; mt < 4; mt++) {
        #pragma unroll
        for (int nt = 0; nt < 4; nt++) {
            int gm = m0 + wm + mt * 16 + (lane >> 2);
            int gn = n0 + wn + nt * 8 + (lane & 3) * 2;
            float b0 = __ldg(bias + gn);
            float b1 = __ldg(bias + gn + 1);
            __half2 h0 = __floats2half2_rn(acc[mt][nt][0] + b0, acc[mt][nt][1] + b1);
            __half2 h1 = __floats2half2_rn(acc[mt][nt][2] + b0, acc[mt][nt][3] + b1);
            *reinterpret_cast<__half2*>(&g_qkvh[(size_t)gm * COUT + gn]) = h0;
            *reinterpret_cast<__half2*>(&g_qkvh[(size_t)(gm + 8) * COUT + gn]) = h1;
        }
    }
}

// ---------------------------------------------------------------------------
// Kernel 2: attention + LePE + scatter. All gmem traffic row-coalesced:
// q/k/v gathered fp16 -> fp32 smem; O staged in smem (reuses sq) and then
// scattered with 8-lane-per-row stores.
// ---------------------------------------------------------------------------
__device__ __forceinline__ void cvt8(float* dst, uint4 r) {
    const __half2* h = reinterpret_cast<const __half2*>(&r);
    float2 f0 = __half22float2(h[0]);
    float2 f1 = __half22float2(h[1]);
    float2 f2 = __half22float2(h[2]);
    float2 f3 = __half22float2(h[3]);
    float4 a = {f0.x, f0.y, f1.x, f1.y};
    float4 b = {f2.x, f2.y, f3.x, f3.y};
    reinterpret_cast<float4*>(dst)[0] = a;
    reinterpret_cast<float4*>(dst)[1] = b;
}

__global__ __launch_bounds__(128) void attn_kernel(const float* __restrict__ lepe_w,
                                                   const float* __restrict__ lepe_b,
                                                   float* __restrict__ out) {
    const int head = blockIdx.y;
    const int w    = blockIdx.x;
    const int b    = w >> 6;
    const int wi   = w & 63;
    const int wh   = wi >> 3;
    const int ww   = wi & 7;

    __shared__ alignas(16) float sq[49 * 36];      // q, later reused as O
    __shared__ alignas(16) float sk[49 * 36];
    __shared__ alignas(16) float sv[49 * 36];
    __shared__ alignas(16) float S[49 * 53];
    __shared__ alignas(16) float swgt[9 * 32];     // [tap][j]
    __shared__ int   stok[49];
    __shared__ int   sreg[49];

    const int tid = threadIdx.x;

    if (tid < 49) {
        int r = tid / 7, c = tid - (tid / 7) * 7;
        int ys = wh * 7 + r;
        int xs = ww * 7 + c;
        int y = ys + 3; if (y >= 56) y -= 56;
        int x = xs + 3; if (x >= 56) x -= 56;
        stok[tid] = b * 3136 + y * 56 + x;
        int rh = (ys < 49) ? 0 : ((ys < 53) ? 1 : 2);
        int rw = (xs < 49) ? 0 : ((xs < 53) ? 1 : 2);
        sreg[tid] = rh * 3 + rw;
    }
    for (int i = tid; i < 9 * 32; i += 128) {
        int tap = i >> 5, j = i & 31;
        swgt[i] = lepe_w[head * 288 + j * 9 + tap];
    }
    __syncthreads();

    // Gather q,k,v (row-coalesced fp16 loads, convert to fp32 smem)
    for (int i = tid; i < 49 * 4; i += 128) {
        int n = i >> 2, u = i & 3;
        const uint4* base = reinterpret_cast<const uint4*>(
            g_qkvh + (size_t)stok[n] * COUT + head * 32);
        cvt8(sq + n * 36 + u * 8, base[u]);
        cvt8(sk + n * 36 + u * 8, base[CIN / 8 + u]);
        cvt8(sv + n * 36 + u * 8, base[2 * CIN / 8 + u]);
    }
    __syncthreads();

    // S = q k^T * scale + mask.  half = tid>>6 (warp-aligned), ii = tid&63.
    const float scale = 0.17677669529663687f;
    {
        const int half = tid >> 6;
        const int ii   = tid & 63;
        if (ii < 49) {
            float4 q[8];
            const float4* qr = reinterpret_cast<const float4*>(sq + ii * 36);
            #pragma unroll
            for (int u = 0; u < 8; u++) q[u] = qr[u];
            const int regi = sreg[ii];
            const int mlo = half ? 25 : 0;
            const int mhi = half ? 49 : 25;
            float* Srow = S + ii * 53;
            for (int m = mlo; m < mhi; m++) {
                const float4* kr = reinterpret_cast<const float4*>(sk + m * 36);
                float a = 0.0f;
                #pragma unroll
                for (int u = 0; u < 8; u++) {
                    float4 kv = kr[u];
                    a = fmaf(q[u].x, kv.x, a);
                    a = fmaf(q[u].y, kv.y, a);
                    a = fmaf(q[u].z, kv.z, a);
                    a = fmaf(q[u].w, kv.w, a);
                }
                a *= scale;
                if (regi != sreg[m]) a -= 100.0f;
                Srow[m] = a;
            }
        }
    }
    __syncthreads();

    // softmax rows
    if (tid < 49) {
        float* row = S + tid * 53;
        float mx = row[0];
        for (int m = 1; m < 49; m++) mx = fmaxf(mx, row[m]);
        float sum = 0.0f;
        for (int m = 0; m < 49; m++) {
            float e = __expf(row[m] - mx);
            row[m] = e;
            sum += e;
        }
        float inv = 1.0f / sum;
        for (int m = 0; m < 49; m++) row[m] *= inv;
    }
    __syncthreads();

    // O = P v + LePE -> staged into sq (q is dead)
    {
        const int half = tid >> 6;
        const int n    = tid & 63;
        if (n < 49) {
            const int j0 = half * 16;
            float4 acc[4] = {};
            const float* Srow = S + n * 53;
            for (int m = 0; m < 49; m++) {
                float p = Srow[m];
                const float4* vr = reinterpret_cast<const float4*>(sv + m * 36 + j0);
                #pragma unroll
                for (int c = 0; c < 4; c++) {
                    float4 vv = vr[c];
                    acc[c].x = fmaf(p, vv.x, acc[c].x);
                    acc[c].y = fmaf(p, vv.y, acc[c].y);
                    acc[c].z = fmaf(p, vv.z, acc[c].z);
                    acc[c].w = fmaf(p, vv.w, acc[c].w);
                }
            }
            // LePE
            float4 lp[4];
            #pragma unroll
            for (int c = 0; c < 4; c++)
                lp[c] = __ldg(reinterpret_cast<const float4*>(lepe_b + head * 32 + j0) + c);
            const int rr = n / 7, cc = n - (n / 7) * 7;
            #pragma unroll
            for (int dy = 0; dy < 3; dy++) {
                int y2 = rr + dy - 1;
                if ((unsigned)y2 >= 7u) continue;
                #pragma unroll
                for (int dx = 0; dx < 3; dx++) {
                    int x2 = cc + dx - 1;
                    if ((unsigned)x2 >= 7u) continue;
                    const int tap = dy * 3 + dx;
                    const float4* vr = reinterpret_cast<const float4*>(
                        sv + (y2 * 7 + x2) * 36 + j0);
                    const float4* wt = reinterpret_cast<const float4*>(swgt + tap * 32 + j0);
                    #pragma unroll
                    for (int c = 0; c < 4; c++) {
                        float4 vv = vr[c], ww2 = wt[c];
                        lp[c].x = fmaf(vv.x, ww2.x, lp[c].x);
                        lp[c].y = fmaf(vv.y, ww2.y, lp[c].y);
                        lp[c].z = fmaf(vv.z, ww2.z, lp[c].z);
                        lp[c].w = fmaf(vv.w, ww2.w, lp[c].w);
                    }
                }
            }
            float4* dst = reinterpret_cast<float4*>(sq + n * 36 + j0);
            #pragma unroll
            for (int c = 0; c < 4; c++) {
                float4 o;
                o.x = acc[c].x + lp[c].x;
                o.y = acc[c].y + lp[c].y;
                o.z = acc[c].z + lp[c].z;
                o.w = acc[c].w + lp[c].w;
                dst[c] = o;
            }
        }
    }
    __syncthreads();

    // Row-coalesced scatter to gmem
    for (int i = tid; i < 49 * 8; i += 128) {
        int n = i >> 3, u = i & 7;
        reinterpret_cast<float4*>(out + (size_t)stok[n] * CIN + head * 32)[u] =
            reinterpret_cast<const float4*>(sq + n * 36)[u];
    }
}

// ---------------------------------------------------------------------------
extern "C" void kernel_launch(void* const* d_in, const int* in_sizes, int n_in,
                              void* d_out, int out_size) {
    const float* X    = (const float*)d_in[0];   // (32, 3136, 384)
    const float* Wqkv = (const float*)d_in[1];   // (1152, 384)
    const float* bqkv = (const float*)d_in[2];   // (1152,)
    const float* lw   = (const float*)d_in[3];   // (384,1,3,3)
    const float* lb   = (const float*)d_in[4];   // (384,)
    float* out = (float*)d_out;

    cudaFuncSetAttribute(qkv_gemm_mma,
                         cudaFuncAttributeMaxDynamicSharedMemorySize, SMEM_TOTAL_G);

    cvt_f16<<<(TOK * CIN / 4) / 256, 256>>>(X, TOK * CIN / 4, 0);
    cvt_f16<<<(COUT * CIN / 4) / 256, 256>>>(Wqkv, COUT * CIN / 4, 1);
    qkv_gemm_mma<<<dim3(COUT / GBN, TOK / GBM), 256, SMEM_TOTAL_G>>>(bqkv);
    attn_kernel<<<dim3(NWIN, NHEAD), 128>>>(lw, lb, out);
}

// round 9
// speedup vs baseline: 7.3631x; 1.3666x over previous
#include <cuda_runtime.h>
#include <cuda_bf16.h>
#include <cuda_fp16.h>
#include <cstdint>

// Problem constants (fixed shapes)
#define TOK   100352          // B * H * W = 32 * 56 * 56
#define CIN   384
#define COUT  1152
#define NWIN  2048            // B * 64 windows
#define NHEAD 12

// Scratch
__device__ __half g_qkvh[(size_t)TOK * COUT];               // 231 MB (fp16)
__device__ __half g_Xh[(size_t)TOK * CIN];
__device__ __half g_Wh[(size_t)COUT * CIN];

// ---------------------------------------------------------------------------
// Kernel 0: fp32 -> fp16
// ---------------------------------------------------------------------------
__global__ __launch_bounds__(256) void cvt_f16(const float* __restrict__ src,
                                               int n4, int which) {
    __half* dst = which ? g_Wh : g_Xh;
    int i = blockIdx.x * blockDim.x + threadIdx.x;
    if (i >= n4) return;
    float4 v = reinterpret_cast<const float4*>(src)[i];
    __half2 h0 = __floats2half2_rn(v.x, v.y);
    __half2 h1 = __floats2half2_rn(v.z, v.w);
    reinterpret_cast<__half2*>(dst)[2 * i]     = h0;
    reinterpret_cast<__half2*>(dst)[2 * i + 1] = h1;
}

// Shared swizzle: rows of 64B (32 fp16), chunk c (16B, 0..3) of row r at
// (r>>1)*128 + (((r&1)*4+c) ^ ((r>>1)&7))*16 -> conflict-free ldmatrix.
__device__ __forceinline__ uint32_t tile_off(int r, int c) {
    return (uint32_t)((r >> 1) * 128 + ((((r & 1) * 4 + c) ^ ((r >> 1) & 7)) << 4));
}

#define LDSM4(R, addr) \
    asm volatile("ldmatrix.sync.aligned.m8n8.x4.shared.b16 {%0,%1,%2,%3}, [%4];" \
        : "=r"((R)[0]), "=r"((R)[1]), "=r"((R)[2]), "=r"((R)[3]) : "r"(addr))
#define LDSM2(R, addr) \
    asm volatile("ldmatrix.sync.aligned.m8n8.x2.shared.b16 {%0,%1}, [%2];" \
        : "=r"((R)[0]), "=r"((R)[1]) : "r"(addr))
#define LDSM2T(R, addr) \
    asm volatile("ldmatrix.sync.aligned.m8n8.x2.trans.shared.b16 {%0,%1}, [%2];" \
        : "=r"((R)[0]), "=r"((R)[1]) : "r"(addr))
#define MMA16816F16(C, A, B) \
    asm volatile("mma.sync.aligned.m16n8k16.row.col.f32.f16.f16.f32 " \
        "{%0,%1,%2,%3}, {%4,%5,%6,%7}, {%8,%9}, {%0,%1,%2,%3};" \
        : "+f"((C)[0]), "+f"((C)[1]), "+f"((C)[2]), "+f"((C)[3]) \
        : "r"((A)[0]), "r"((A)[1]), "r"((A)[2]), "r"((A)[3]), \
          "r"((B)[0]), "r"((B)[1]))
#define CPASYNC16(dst, src) \
    asm volatile("cp.async.cg.shared.global [%0], [%1], 16;" :: "r"(dst), "l"(src))

// ---------------------------------------------------------------------------
// Kernel 1: QKV GEMM  Y = X @ W^T + b  (fp16 mma, fp32 accum, fp16 out)
// ---------------------------------------------------------------------------
#define GBM 128
#define GBN 128
#define GBK 32
#define STAGE_BYTES 16384
#define NIT 12
#define SMEM_TOTAL_G (3 * STAGE_BYTES)

__global__ __launch_bounds__(256, 2) void qkv_gemm_mma(const float* __restrict__ bias) {
    extern __shared__ char sm_raw[];
    const uint32_t sbase = (uint32_t)__cvta_generic_to_shared(sm_raw);
    const int tid  = threadIdx.x;
    const int lane = tid & 31;
    const int warp = tid >> 5;
    const int n0 = blockIdx.x * GBN;
    const int m0 = blockIdx.y * GBM;
    const int wm = (warp >> 2) * 64;
    const int wn = (warp & 3) * 32;

    float acc[4][4][4];
    #pragma unroll
    for (int a = 0; a < 4; a++)
        #pragma unroll
        for (int b = 0; b < 4; b++)
            #pragma unroll
            for (int c = 0; c < 4; c++) acc[a][b][c] = 0.0f;

    auto load_stage = [&](int st) {
        const int k0 = st * GBK;
        uint32_t abase = sbase + (st % 3) * STAGE_BYTES;
        uint32_t bbase = abase + 8192;
        #pragma unroll
        for (int u = 0; u < 2; u++) {
            int q = tid * 2 + u;
            int r = q >> 2, c = q & 3;
            uint32_t soff = tile_off(r, c);
            CPASYNC16(abase + soff, g_Xh + (size_t)(m0 + r) * CIN + k0 + c * 8);
            CPASYNC16(bbase + soff, g_Wh + (size_t)(n0 + r) * CIN + k0 + c * 8);
        }
        asm volatile("cp.async.commit_group;");
    };

    load_stage(0);
    load_stage(1);

    #pragma unroll 1
    for (int it = 0; it < NIT; it++) {
        if (it + 1 < NIT) asm volatile("cp.async.wait_group 1;");
        else              asm volatile("cp.async.wait_group 0;");
        __syncthreads();
        if (it + 2 < NIT) load_stage(it + 2);

        uint32_t abase = sbase + (it % 3) * STAGE_BYTES;
        uint32_t bbase = abase + 8192;

        #pragma unroll
        for (int kk = 0; kk < 2; kk++) {
            uint32_t Ah[4][4], Bh[4][2];
            int arow_in = lane & 15;
            int acol    = lane >> 4;
            #pragma unroll
            for (int mt = 0; mt < 4; mt++) {
                int row = wm + mt * 16 + arow_in;
                LDSM4(Ah[mt], abase + tile_off(row, kk * 2 + acol));
            }
            int lb = lane & 15;
            int brow_in = lb & 7;
            int bcol    = lb >> 3;
            #pragma unroll
            for (int nt = 0; nt < 4; nt++) {
                int row = wn + nt * 8 + brow_in;
                LDSM2(Bh[nt], bbase + tile_off(row, kk * 2 + bcol));
            }
            #pragma unroll
            for (int mt = 0; mt < 4; mt++)
                #pragma unroll
                for (int nt = 0; nt < 4; nt++)
                    MMA16816F16(acc[mt][nt], Ah[mt], Bh[nt]);
        }
    }

    #pragma unroll
    for (int mt = 0; mt < 4; mt++) {
        #pragma unroll
        for (int nt = 0; nt < 4; nt++) {
            int gm = m0 + wm + mt * 16 + (lane >> 2);
            int gn = n0 + wn + nt * 8 + (lane & 3) * 2;
            float b0 = __ldg(bias + gn);
            float b1 = __ldg(bias + gn + 1);
            __half2 h0 = __floats2half2_rn(acc[mt][nt][0] + b0, acc[mt][nt][1] + b1);
            __half2 h1 = __floats2half2_rn(acc[mt][nt][2] + b0, acc[mt][nt][3] + b1);
            *reinterpret_cast<__half2*>(&g_qkvh[(size_t)gm * COUT + gn]) = h0;
            *reinterpret_cast<__half2*>(&g_qkvh[(size_t)(gm + 8) * COUT + gn]) = h1;
        }
    }
}

// ---------------------------------------------------------------------------
// Kernel 2: tensor-core attention + scalar LePE + scatter.
// Tokens padded 49->64. Warp w owns S rows [16w,16w+16).
// S = Q K^T via mma (A: Q ldmatrix, B: K ldmatrix, as in QKV GEMM).
// Softmax in registers (4-lane shfl). P repacked in-register to A frags.
// O = P V via mma (B: V ldmatrix.trans).
// ---------------------------------------------------------------------------
__global__ __launch_bounds__(128) void attn_kernel(const float* __restrict__ lepe_w,
                                                   const float* __restrict__ lepe_b,
                                                   float* __restrict__ out) {
    const int head = blockIdx.y;
    const int w    = blockIdx.x;
    const int b    = w >> 6;
    const int wi   = w & 63;
    const int wh   = wi >> 3;
    const int ww   = wi & 7;

    __shared__ alignas(16) __half sQ[64 * 32];
    __shared__ alignas(16) __half sK[64 * 32];
    __shared__ alignas(16) __half sV[64 * 32];
    __shared__ alignas(16) float sO[49 * 36];
    __shared__ alignas(16) float swgt[9 * 32];
    __shared__ unsigned long long sM[49];
    __shared__ int stok[49];
    __shared__ int sreg[49];

    const int tid  = threadIdx.x;
    const int warp = tid >> 5;
    const int lane = tid & 31;

    if (tid < 49) {
        int r = tid / 7, c = tid - (tid / 7) * 7;
        int ys = wh * 7 + r;
        int xs = ww * 7 + c;
        int y = ys + 3; if (y >= 56) y -= 56;
        int x = xs + 3; if (x >= 56) x -= 56;
        stok[tid] = b * 3136 + y * 56 + x;
        int rh = (ys < 49) ? 0 : ((ys < 53) ? 1 : 2);
        int rw = (xs < 49) ? 0 : ((xs < 53) ? 1 : 2);
        sreg[tid] = rh * 3 + rw;
    }
    for (int i = tid; i < 9 * 32; i += 128) {
        int tap = i >> 5, j = i & 31;
        swgt[i] = lepe_w[head * 288 + j * 9 + tap];
    }
    __syncthreads();

    // mask bits per row
    if (tid < 49) {
        unsigned long long bits = 0ull;
        int ri = sreg[tid];
        for (int m = 0; m < 49; m++)
            bits |= (unsigned long long)(sreg[m] != ri) << m;
        sM[tid] = bits;
    }
    // zero pad rows 49..63 (15 rows x 4 chunks x 3 tensors)
    for (int i = tid; i < 180; i += 128) {
        int tens = i / 60, rem = i - tens * 60;
        int r = 49 + (rem >> 2), c = rem & 3;
        char* base = (tens == 0) ? (char*)sQ : (tens == 1) ? (char*)sK : (char*)sV;
        *reinterpret_cast<uint4*>(base + tile_off(r, c)) = make_uint4(0, 0, 0, 0);
    }
    // gather q,k,v rows (fp16, swizzled)
    for (int i = tid; i < 196; i += 128) {
        int n = i >> 2, c = i & 3;
        const uint4* src = reinterpret_cast<const uint4*>(
            g_qkvh + (size_t)stok[n] * COUT + head * 32);
        *reinterpret_cast<uint4*>((char*)sQ + tile_off(n, c)) = src[c];
        *reinterpret_cast<uint4*>((char*)sK + tile_off(n, c)) = src[48 + c];
        *reinterpret_cast<uint4*>((char*)sV + tile_off(n, c)) = src[96 + c];
    }
    __syncthreads();

    const uint32_t qb = (uint32_t)__cvta_generic_to_shared(sQ);
    const uint32_t kb = (uint32_t)__cvta_generic_to_shared(sK);
    const uint32_t vb = (uint32_t)__cvta_generic_to_shared(sV);

    // ---- S = Q K^T (per warp: rows [16w, 16w+16), all 64 cols) ----
    const int i0 = warp * 16;
    float acc[8][4];
    #pragma unroll
    for (int nt = 0; nt < 8; nt++)
        #pragma unroll
        for (int c = 0; c < 4; c++) acc[nt][c] = 0.0f;

    #pragma unroll
    for (int kk = 0; kk < 2; kk++) {
        uint32_t A[4];
        LDSM4(A, qb + tile_off(i0 + (lane & 15), kk * 2 + (lane >> 4)));
        #pragma unroll
        for (int nt = 0; nt < 8; nt++) {
            uint32_t B[2];
            LDSM2(B, kb + tile_off(nt * 8 + (lane & 7), kk * 2 + ((lane >> 3) & 1)));
            MMA16816F16(acc[nt], A, B);
        }
    }

    // ---- scale + mask ----
    const float scale = 0.17677669529663687f;
    const int r0 = i0 + (lane >> 2);
    const int r1 = r0 + 8;
    const unsigned long long mb0 = sM[min(r0, 48)];
    const unsigned long long mb1 = sM[min(r1, 48)];
    #pragma unroll
    for (int nt = 0; nt < 8; nt++) {
        const int cb = nt * 8 + (lane & 3) * 2;
        float s0 = acc[nt][0] * scale;
        float s1 = acc[nt][1] * scale;
        float s2 = acc[nt][2] * scale;
        float s3 = acc[nt][3] * scale;
        if (cb >= 49)      s0 = -1e30f; else if ((mb0 >> cb) & 1)       s0 -= 100.0f;
        if (cb + 1 >= 49)  s1 = -1e30f; else if ((mb0 >> (cb + 1)) & 1) s1 -= 100.0f;
        if (cb >= 49)      s2 = -1e30f; else if ((mb1 >> cb) & 1)       s2 -= 100.0f;
        if (cb + 1 >= 49)  s3 = -1e30f; else if ((mb1 >> (cb + 1)) & 1) s3 -= 100.0f;
        acc[nt][0] = s0; acc[nt][1] = s1; acc[nt][2] = s2; acc[nt][3] = s3;
    }

    // ---- softmax over rows r0 (c0,c1) and r1 (c2,c3); 4-lane groups ----
    float mx0 = -1e30f, mx1 = -1e30f;
    #pragma unroll
    for (int nt = 0; nt < 8; nt++) {
        mx0 = fmaxf(mx0, fmaxf(acc[nt][0], acc[nt][1]));
        mx1 = fmaxf(mx1, fmaxf(acc[nt][2], acc[nt][3]));
    }
    mx0 = fmaxf(mx0, __shfl_xor_sync(0xffffffff, mx0, 1));
    mx0 = fmaxf(mx0, __shfl_xor_sync(0xffffffff, mx0, 2));
    mx1 = fmaxf(mx1, __shfl_xor_sync(0xffffffff, mx1, 1));
    mx1 = fmaxf(mx1, __shfl_xor_sync(0xffffffff, mx1, 2));
    float sum0 = 0.0f, sum1 = 0.0f;
    #pragma unroll
    for (int nt = 0; nt < 8; nt++) {
        acc[nt][0] = __expf(acc[nt][0] - mx0); sum0 += acc[nt][0];
        acc[nt][1] = __expf(acc[nt][1] - mx0); sum0 += acc[nt][1];
        acc[nt][2] = __expf(acc[nt][2] - mx1); sum1 += acc[nt][2];
        acc[nt][3] = __expf(acc[nt][3] - mx1); sum1 += acc[nt][3];
    }
    sum0 += __shfl_xor_sync(0xffffffff, sum0, 1);
    sum0 += __shfl_xor_sync(0xffffffff, sum0, 2);
    sum1 += __shfl_xor_sync(0xffffffff, sum1, 1);
    sum1 += __shfl_xor_sync(0xffffffff, sum1, 2);
    const float inv0 = 1.0f / sum0;
    const float inv1 = 1.0f / sum1;

    // ---- pack P into A fragments (kstep k covers S cols [16k,16k+16)) ----
    uint32_t Pa[4][4];
    #pragma unroll
    for (int k = 0; k < 4; k++) {
        __half2 h;
        h = __floats2half2_rn(acc[2 * k][0] * inv0, acc[2 * k][1] * inv0);
        Pa[k][0] = *reinterpret_cast<uint32_t*>(&h);
        h = __floats2half2_rn(acc[2 * k][2] * inv1, acc[2 * k][3] * inv1);
        Pa[k][1] = *reinterpret_cast<uint32_t*>(&h);
        h = __floats2half2_rn(acc[2 * k + 1][0] * inv0, acc[2 * k + 1][1] * inv0);
        Pa[k][2] = *reinterpret_cast<uint32_t*>(&h);
        h = __floats2half2_rn(acc[2 * k + 1][2] * inv1, acc[2 * k + 1][3] * inv1);
        Pa[k][3] = *reinterpret_cast<uint32_t*>(&h);
    }

    // ---- O = P V  (K=64 tokens, N=32 channels) ----
    float oacc[4][4];
    #pragma unroll
    for (int nt = 0; nt < 4; nt++)
        #pragma unroll
        for (int c = 0; c < 4; c++) oacc[nt][c] = 0.0f;
    #pragma unroll
    for (int k = 0; k < 4; k++) {
        #pragma unroll
        for (int nt = 0; nt < 4; nt++) {
            uint32_t B[2];
            LDSM2T(B, vb + tile_off(k * 16 + (lane & 15), nt));
            MMA16816F16(oacc[nt], Pa[k], B);
        }
    }

    // ---- stage O (attention part) into sO ----
    #pragma unroll
    for (int nt = 0; nt < 4; nt++) {
        const int j = nt * 8 + (lane & 3) * 2;
        if (r0 < 49)
            *reinterpret_cast<float2*>(&sO[r0 * 36 + j]) =
                make_float2(oacc[nt][0], oacc[nt][1]);
        if (r1 < 49)
            *reinterpret_cast<float2*>(&sO[r1 * 36 + j]) =
                make_float2(oacc[nt][2], oacc[nt][3]);
    }
    __syncthreads();

    // ---- LePE (depthwise 3x3 on v) added into sO ----
    {
        const int half = tid >> 6;
        const int n    = tid & 63;
        if (n < 49) {
            const int j0 = half * 16;
            const int rr = n / 7, cc = n - (n / 7) * 7;
            float2 lp[8];
            #pragma unroll
            for (int c = 0; c < 8; c++) {
                int j = j0 + c * 2;
                lp[c] = make_float2(__ldg(lepe_b + head * 32 + j),
                                    __ldg(lepe_b + head * 32 + j + 1));
            }
            #pragma unroll
            for (int dy = 0; dy < 3; dy++) {
                int y2 = rr + dy - 1;
                if ((unsigned)y2 >= 7u) continue;
                #pragma unroll
                for (int dx = 0; dx < 3; dx++) {
                    int x2 = cc + dx - 1;
                    if ((unsigned)x2 >= 7u) continue;
                    const int tap = dy * 3 + dx;
                    const int m = y2 * 7 + x2;
                    #pragma unroll
                    for (int c = 0; c < 8; c++) {
                        int j = j0 + c * 2;
                        const __half2 vh = *reinterpret_cast<const __half2*>(
                            (const char*)sV + tile_off(m, j >> 3) + (j & 7) * 2);
                        float2 vf = __half22float2(vh);
                        float w0 = swgt[tap * 32 + j];
                        float w1 = swgt[tap * 32 + j + 1];
                        lp[c].x = fmaf(vf.x, w0, lp[c].x);
                        lp[c].y = fmaf(vf.y, w1, lp[c].y);
                    }
                }
            }
            #pragma unroll
            for (int c = 0; c < 8; c++) {
                int j = j0 + c * 2;
                float2* p = reinterpret_cast<float2*>(&sO[n * 36 + j]);
                float2 o = *p;
                o.x += lp[c].x;
                o.y += lp[c].y;
                *p = o;
            }
        }
    }
    __syncthreads();

    // ---- row-coalesced scatter ----
    for (int i = tid; i < 49 * 8; i += 128) {
        int n = i >> 3, u = i & 7;
        reinterpret_cast<float4*>(out + (size_t)stok[n] * CIN + head * 32)[u] =
            reinterpret_cast<const float4*>(sO + n * 36)[u];
    }
}

// ---------------------------------------------------------------------------
extern "C" void kernel_launch(void* const* d_in, const int* in_sizes, int n_in,
                              void* d_out, int out_size) {
    const float* X    = (const float*)d_in[0];   // (32, 3136, 384)
    const float* Wqkv = (const float*)d_in[1];   // (1152, 384)
    const float* bqkv = (const float*)d_in[2];   // (1152,)
    const float* lw   = (const float*)d_in[3];   // (384,1,3,3)
    const float* lb   = (const float*)d_in[4];   // (384,)
    float* out = (float*)d_out;

    cudaFuncSetAttribute(qkv_gemm_mma,
                         cudaFuncAttributeMaxDynamicSharedMemorySize, SMEM_TOTAL_G);

    cvt_f16<<<(TOK * CIN / 4) / 256, 256>>>(X, TOK * CIN / 4, 0);
    cvt_f16<<<(COUT * CIN / 4) / 256, 256>>>(Wqkv, COUT * CIN / 4, 1);
    qkv_gemm_mma<<<dim3(COUT / GBN, TOK / GBM), 256, SMEM_TOTAL_G>>>(bqkv);
    attn_kernel<<<dim3(NWIN, NHEAD), 128>>>(lw, lb, out);
}

// round 10
// speedup vs baseline: 7.7034x; 1.0462x over previous
#include <cuda_runtime.h>
#include <cuda_bf16.h>
#include <cuda_fp16.h>
#include <cstdint>

// Problem constants (fixed shapes)
#define TOK   100352          // B * H * W = 32 * 56 * 56
#define CIN   384
#define COUT  1152
#define NWIN  2048            // B * 64 windows
#define NHEAD 12

// Scratch
__device__ __half g_qkvh[(size_t)TOK * COUT];               // 231 MB (fp16)
__device__ __half g_Xh[(size_t)TOK * CIN];
__device__ __half g_Wh[(size_t)COUT * CIN];
__device__ int g_tokoff[64 * 49];
__device__ unsigned long long g_wmask[64 * 49];

// ---------------------------------------------------------------------------
// Kernel 0a: fp32 -> fp16
// ---------------------------------------------------------------------------
__global__ __launch_bounds__(256) void cvt_f16(const float* __restrict__ src,
                                               int n4, int which) {
    __half* dst = which ? g_Wh : g_Xh;
    int i = blockIdx.x * blockDim.x + threadIdx.x;
    if (i >= n4) return;
    float4 v = reinterpret_cast<const float4*>(src)[i];
    __half2 h0 = __floats2half2_rn(v.x, v.y);
    __half2 h1 = __floats2half2_rn(v.z, v.w);
    reinterpret_cast<__half2*>(dst)[2 * i]     = h0;
    reinterpret_cast<__half2*>(dst)[2 * i + 1] = h1;
}

// ---------------------------------------------------------------------------
// Kernel 0b: per-window-type token map + shift-mask tables (64 x 49)
// ---------------------------------------------------------------------------
__global__ void win_setup() {
    __shared__ int sreg[49];
    const int wi = blockIdx.x;
    const int n  = threadIdx.x;          // 0..48
    const int wh = wi >> 3, ww = wi & 7;
    const int r = n / 7, c = n - (n / 7) * 7;
    const int ys = wh * 7 + r;
    const int xs = ww * 7 + c;
    int y = ys + 3; if (y >= 56) y -= 56;
    int x = xs + 3; if (x >= 56) x -= 56;
    g_tokoff[wi * 49 + n] = y * 56 + x;
    const int rh = (ys < 49) ? 0 : ((ys < 53) ? 1 : 2);
    const int rw = (xs < 49) ? 0 : ((xs < 53) ? 1 : 2);
    sreg[n] = rh * 3 + rw;
    __syncthreads();
    unsigned long long bits = 0ull;
    const int ri = sreg[n];
    for (int m = 0; m < 49; m++)
        bits |= (unsigned long long)(sreg[m] != ri) << m;
    g_wmask[wi * 49 + n] = bits;
}

// Shared swizzle: rows of 64B (32 fp16), chunk c (16B, 0..3) of row r at
// (r>>1)*128 + (((r&1)*4+c) ^ ((r>>1)&7))*16 -> conflict-free ldmatrix.
__device__ __forceinline__ uint32_t tile_off(int r, int c) {
    return (uint32_t)((r >> 1) * 128 + ((((r & 1) * 4 + c) ^ ((r >> 1) & 7)) << 4));
}

#define LDSM4(R, addr) \
    asm volatile("ldmatrix.sync.aligned.m8n8.x4.shared.b16 {%0,%1,%2,%3}, [%4];" \
        : "=r"((R)[0]), "=r"((R)[1]), "=r"((R)[2]), "=r"((R)[3]) : "r"(addr))
#define LDSM2(R, addr) \
    asm volatile("ldmatrix.sync.aligned.m8n8.x2.shared.b16 {%0,%1}, [%2];" \
        : "=r"((R)[0]), "=r"((R)[1]) : "r"(addr))
#define LDSM2T(R, addr) \
    asm volatile("ldmatrix.sync.aligned.m8n8.x2.trans.shared.b16 {%0,%1}, [%2];" \
        : "=r"((R)[0]), "=r"((R)[1]) : "r"(addr))
#define MMA16816F16(C, A, B) \
    asm volatile("mma.sync.aligned.m16n8k16.row.col.f32.f16.f16.f32 " \
        "{%0,%1,%2,%3}, {%4,%5,%6,%7}, {%8,%9}, {%0,%1,%2,%3};" \
        : "+f"((C)[0]), "+f"((C)[1]), "+f"((C)[2]), "+f"((C)[3]) \
        : "r"((A)[0]), "r"((A)[1]), "r"((A)[2]), "r"((A)[3]), \
          "r"((B)[0]), "r"((B)[1]))
#define CPASYNC16(dst, src) \
    asm volatile("cp.async.cg.shared.global [%0], [%1], 16;" :: "r"(dst), "l"(src))

// ---------------------------------------------------------------------------
// Kernel 1: QKV GEMM  Y = X @ W^T + b  (fp16 mma, fp32 accum, fp16 out)
// 4-stage cp.async; B loaded with x4 ldmatrix (two n8 tiles per issue).
// ---------------------------------------------------------------------------
#define GBM 128
#define GBN 128
#define GBK 32
#define STAGE_BYTES 16384
#define NIT 12
#define NPIPE 4
#define SMEM_TOTAL_G (NPIPE * STAGE_BYTES)

__global__ __launch_bounds__(256, 2) void qkv_gemm_mma(const float* __restrict__ bias) {
    extern __shared__ char sm_raw[];
    const uint32_t sbase = (uint32_t)__cvta_generic_to_shared(sm_raw);
    const int tid  = threadIdx.x;
    const int lane = tid & 31;
    const int warp = tid >> 5;
    const int n0 = blockIdx.x * GBN;
    const int m0 = blockIdx.y * GBM;
    const int wm = (warp >> 2) * 64;
    const int wn = (warp & 3) * 32;

    float acc[4][4][4];
    #pragma unroll
    for (int a = 0; a < 4; a++)
        #pragma unroll
        for (int b = 0; b < 4; b++)
            #pragma unroll
            for (int c = 0; c < 4; c++) acc[a][b][c] = 0.0f;

    auto load_stage = [&](int st) {
        const int k0 = st * GBK;
        uint32_t abase = sbase + (st % NPIPE) * STAGE_BYTES;
        uint32_t bbase = abase + 8192;
        #pragma unroll
        for (int u = 0; u < 2; u++) {
            int q = tid * 2 + u;
            int r = q >> 2, c = q & 3;
            uint32_t soff = tile_off(r, c);
            CPASYNC16(abase + soff, g_Xh + (size_t)(m0 + r) * CIN + k0 + c * 8);
            CPASYNC16(bbase + soff, g_Wh + (size_t)(n0 + r) * CIN + k0 + c * 8);
        }
        asm volatile("cp.async.commit_group;");
    };

    load_stage(0);
    load_stage(1);
    load_stage(2);

    #pragma unroll 1
    for (int it = 0; it < NIT; it++) {
        if (it + 3 < NIT) asm volatile("cp.async.wait_group 2;");
        else              asm volatile("cp.async.wait_group 0;");
        __syncthreads();
        if (it + 3 < NIT) load_stage(it + 3);

        uint32_t abase = sbase + (it % NPIPE) * STAGE_BYTES;
        uint32_t bbase = abase + 8192;

        #pragma unroll
        for (int kk = 0; kk < 2; kk++) {
            uint32_t Ah[4][4], Bh[2][4];
            int arow_in = lane & 15;
            int acol    = lane >> 4;
            #pragma unroll
            for (int mt = 0; mt < 4; mt++) {
                int row = wm + mt * 16 + arow_in;
                LDSM4(Ah[mt], abase + tile_off(row, kk * 2 + acol));
            }
            // B: one x4 per n16 pair: lane-group g -> tile (np*2+(g>>1), kchunk g&1)
            const int g = lane >> 3;
            #pragma unroll
            for (int np = 0; np < 2; np++) {
                int row = wn + (np * 2 + (g >> 1)) * 8 + (lane & 7);
                LDSM4(Bh[np], bbase + tile_off(row, kk * 2 + (g & 1)));
            }
            #pragma unroll
            for (int mt = 0; mt < 4; mt++)
                #pragma unroll
                for (int nt = 0; nt < 4; nt++)
                    MMA16816F16(acc[mt][nt], Ah[mt], &Bh[nt >> 1][(nt & 1) * 2]);
        }
    }

    #pragma unroll
    for (int mt = 0; mt < 4; mt++) {
        #pragma unroll
        for (int nt = 0; nt < 4; nt++) {
            int gm = m0 + wm + mt * 16 + (lane >> 2);
            int gn = n0 + wn + nt * 8 + (lane & 3) * 2;
            float b0 = __ldg(bias + gn);
            float b1 = __ldg(bias + gn + 1);
            __half2 h0 = __floats2half2_rn(acc[mt][nt][0] + b0, acc[mt][nt][1] + b1);
            __half2 h1 = __floats2half2_rn(acc[mt][nt][2] + b0, acc[mt][nt][3] + b1);
            *reinterpret_cast<__half2*>(&g_qkvh[(size_t)gm * COUT + gn]) = h0;
            *reinterpret_cast<__half2*>(&g_qkvh[(size_t)(gm + 8) * COUT + gn]) = h1;
        }
    }
}

// ---------------------------------------------------------------------------
// Kernel 2: tensor-core attention + scalar LePE + scatter.
// Window-invariant setup comes from g_tokoff / g_wmask tables.
// ---------------------------------------------------------------------------
__global__ __launch_bounds__(128) void attn_kernel(const float* __restrict__ lepe_w,
                                                   const float* __restrict__ lepe_b,
                                                   float* __restrict__ out) {
    const int head = blockIdx.y;
    const int w    = blockIdx.x;
    const int b    = w >> 6;
    const int wi   = w & 63;

    __shared__ alignas(16) __half sQ[64 * 32];
    __shared__ alignas(16) __half sK[64 * 32];
    __shared__ alignas(16) __half sV[64 * 32];
    __shared__ alignas(16) float sO[49 * 36];
    __shared__ alignas(16) float swgt[9 * 32];
    __shared__ int stok[49];

    const int tid  = threadIdx.x;
    const int warp = tid >> 5;
    const int lane = tid & 31;

    if (tid < 49)
        stok[tid] = b * 3136 + __ldg(&g_tokoff[wi * 49 + tid]);
    for (int i = tid; i < 9 * 32; i += 128) {
        int tap = i >> 5, j = i & 31;
        swgt[i] = lepe_w[head * 288 + j * 9 + tap];
    }
    // zero pad rows 49..63 (15 rows x 4 chunks x 3 tensors)
    for (int i = tid; i < 180; i += 128) {
        int tens = i / 60, rem = i - tens * 60;
        int r = 49 + (rem >> 2), c = rem & 3;
        char* base = (tens == 0) ? (char*)sQ : (tens == 1) ? (char*)sK : (char*)sV;
        *reinterpret_cast<uint4*>(base + tile_off(r, c)) = make_uint4(0, 0, 0, 0);
    }
    __syncthreads();

    // gather q,k,v rows (fp16, swizzled)
    for (int i = tid; i < 196; i += 128) {
        int n = i >> 2, c = i & 3;
        const uint4* src = reinterpret_cast<const uint4*>(
            g_qkvh + (size_t)stok[n] * COUT + head * 32);
        *reinterpret_cast<uint4*>((char*)sQ + tile_off(n, c)) = src[c];
        *reinterpret_cast<uint4*>((char*)sK + tile_off(n, c)) = src[48 + c];
        *reinterpret_cast<uint4*>((char*)sV + tile_off(n, c)) = src[96 + c];
    }
    __syncthreads();

    const uint32_t qb = (uint32_t)__cvta_generic_to_shared(sQ);
    const uint32_t kb = (uint32_t)__cvta_generic_to_shared(sK);
    const uint32_t vb = (uint32_t)__cvta_generic_to_shared(sV);

    // ---- S = Q K^T (per warp: rows [16w, 16w+16), all 64 cols) ----
    const int i0 = warp * 16;
    float acc[8][4];
    #pragma unroll
    for (int nt = 0; nt < 8; nt++)
        #pragma unroll
        for (int c = 0; c < 4; c++) acc[nt][c] = 0.0f;

    #pragma unroll
    for (int kk = 0; kk < 2; kk++) {
        uint32_t A[4];
        LDSM4(A, qb + tile_off(i0 + (lane & 15), kk * 2 + (lane >> 4)));
        const int g = lane >> 3;
        #pragma unroll
        for (int np = 0; np < 4; np++) {
            uint32_t B[4];
            int row = (np * 2 + (g >> 1)) * 8 + (lane & 7);
            LDSM4(B, kb + tile_off(row, kk * 2 + (g & 1)));
            MMA16816F16(acc[np * 2],     A, &B[0]);
            MMA16816F16(acc[np * 2 + 1], A, &B[2]);
        }
    }

    // ---- scale + mask (from table) ----
    const float scale = 0.17677669529663687f;
    const int r0 = i0 + (lane >> 2);
    const int r1 = r0 + 8;
    const unsigned long long mb0 = __ldg(&g_wmask[wi * 49 + min(r0, 48)]);
    const unsigned long long mb1 = __ldg(&g_wmask[wi * 49 + min(r1, 48)]);
    #pragma unroll
    for (int nt = 0; nt < 8; nt++) {
        const int cb = nt * 8 + (lane & 3) * 2;
        float s0 = acc[nt][0] * scale;
        float s1 = acc[nt][1] * scale;
        float s2 = acc[nt][2] * scale;
        float s3 = acc[nt][3] * scale;
        if (cb >= 49)      s0 = -1e30f; else if ((mb0 >> cb) & 1)       s0 -= 100.0f;
        if (cb + 1 >= 49)  s1 = -1e30f; else if ((mb0 >> (cb + 1)) & 1) s1 -= 100.0f;
        if (cb >= 49)      s2 = -1e30f; else if ((mb1 >> cb) & 1)       s2 -= 100.0f;
        if (cb + 1 >= 49)  s3 = -1e30f; else if ((mb1 >> (cb + 1)) & 1) s3 -= 100.0f;
        acc[nt][0] = s0; acc[nt][1] = s1; acc[nt][2] = s2; acc[nt][3] = s3;
    }

    // ---- softmax over rows r0 (c0,c1) and r1 (c2,c3); 4-lane groups ----
    float mx0 = -1e30f, mx1 = -1e30f;
    #pragma unroll
    for (int nt = 0; nt < 8; nt++) {
        mx0 = fmaxf(mx0, fmaxf(acc[nt][0], acc[nt][1]));
        mx1 = fmaxf(mx1, fmaxf(acc[nt][2], acc[nt][3]));
    }
    mx0 = fmaxf(mx0, __shfl_xor_sync(0xffffffff, mx0, 1));
    mx0 = fmaxf(mx0, __shfl_xor_sync(0xffffffff, mx0, 2));
    mx1 = fmaxf(mx1, __shfl_xor_sync(0xffffffff, mx1, 1));
    mx1 = fmaxf(mx1, __shfl_xor_sync(0xffffffff, mx1, 2));
    float sum0 = 0.0f, sum1 = 0.0f;
    #pragma unroll
    for (int nt = 0; nt < 8; nt++) {
        acc[nt][0] = __expf(acc[nt][0] - mx0); sum0 += acc[nt][0];
        acc[nt][1] = __expf(acc[nt][1] - mx0); sum0 += acc[nt][1];
        acc[nt][2] = __expf(acc[nt][2] - mx1); sum1 += acc[nt][2];
        acc[nt][3] = __expf(acc[nt][3] - mx1); sum1 += acc[nt][3];
    }
    sum0 += __shfl_xor_sync(0xffffffff, sum0, 1);
    sum0 += __shfl_xor_sync(0xffffffff, sum0, 2);
    sum1 += __shfl_xor_sync(0xffffffff, sum1, 1);
    sum1 += __shfl_xor_sync(0xffffffff, sum1, 2);
    const float inv0 = 1.0f / sum0;
    const float inv1 = 1.0f / sum1;

    // ---- pack P into A fragments (kstep k covers S cols [16k,16k+16)) ----
    uint32_t Pa[4][4];
    #pragma unroll
    for (int k = 0; k < 4; k++) {
        __half2 h;
        h = __floats2half2_rn(acc[2 * k][0] * inv0, acc[2 * k][1] * inv0);
        Pa[k][0] = *reinterpret_cast<uint32_t*>(&h);
        h = __floats2half2_rn(acc[2 * k][2] * inv1, acc[2 * k][3] * inv1);
        Pa[k][1] = *reinterpret_cast<uint32_t*>(&h);
        h = __floats2half2_rn(acc[2 * k + 1][0] * inv0, acc[2 * k + 1][1] * inv0);
        Pa[k][2] = *reinterpret_cast<uint32_t*>(&h);
        h = __floats2half2_rn(acc[2 * k + 1][2] * inv1, acc[2 * k + 1][3] * inv1);
        Pa[k][3] = *reinterpret_cast<uint32_t*>(&h);
    }

    // ---- O = P V  (K=64 tokens, N=32 channels) ----
    float oacc[4][4];
    #pragma unroll
    for (int nt = 0; nt < 4; nt++)
        #pragma unroll
        for (int c = 0; c < 4; c++) oacc[nt][c] = 0.0f;
    #pragma unroll
    for (int k = 0; k < 4; k++) {
        #pragma unroll
        for (int nt = 0; nt < 4; nt++) {
            uint32_t B[2];
            LDSM2T(B, vb + tile_off(k * 16 + (lane & 15), nt));
            MMA16816F16(oacc[nt], Pa[k], B);
        }
    }

    // ---- stage O (attention part) into sO ----
    #pragma unroll
    for (int nt = 0; nt < 4; nt++) {
        const int j = nt * 8 + (lane & 3) * 2;
        if (r0 < 49)
            *reinterpret_cast<float2*>(&sO[r0 * 36 + j]) =
                make_float2(oacc[nt][0], oacc[nt][1]);
        if (r1 < 49)
            *reinterpret_cast<float2*>(&sO[r1 * 36 + j]) =
                make_float2(oacc[nt][2], oacc[nt][3]);
    }
    __syncthreads();

    // ---- LePE (depthwise 3x3 on v) added into sO ----
    {
        const int half = tid >> 6;
        const int n    = tid & 63;
        if (n < 49) {
            const int j0 = half * 16;
            const int rr = n / 7, cc = n - (n / 7) * 7;
            float2 lp[8];
            #pragma unroll
            for (int c = 0; c < 8; c++) {
                int j = j0 + c * 2;
                lp[c] = make_float2(__ldg(lepe_b + head * 32 + j),
                                    __ldg(lepe_b + head * 32 + j + 1));
            }
            #pragma unroll
            for (int dy = 0; dy < 3; dy++) {
                int y2 = rr + dy - 1;
                if ((unsigned)y2 >= 7u) continue;
                #pragma unroll
                for (int dx = 0; dx < 3; dx++) {
                    int x2 = cc + dx - 1;
                    if ((unsigned)x2 >= 7u) continue;
                    const int tap = dy * 3 + dx;
                    const int m = y2 * 7 + x2;
                    #pragma unroll
                    for (int c = 0; c < 8; c++) {
                        int j = j0 + c * 2;
                        const __half2 vh = *reinterpret_cast<const __half2*>(
                            (const char*)sV + tile_off(m, j >> 3) + (j & 7) * 2);
                        float2 vf = __half22float2(vh);
                        float w0 = swgt[tap * 32 + j];
                        float w1 = swgt[tap * 32 + j + 1];
                        lp[c].x = fmaf(vf.x, w0, lp[c].x);
                        lp[c].y = fmaf(vf.y, w1, lp[c].y);
                    }
                }
            }
            #pragma unroll
            for (int c = 0; c < 8; c++) {
                int j = j0 + c * 2;
                float2* p = reinterpret_cast<float2*>(&sO[n * 36 + j]);
                float2 o = *p;
                o.x += lp[c].x;
                o.y += lp[c].y;
                *p = o;
            }
        }
    }
    __syncthreads();

    // ---- row-coalesced scatter ----
    for (int i = tid; i < 49 * 8; i += 128) {
        int n = i >> 3, u = i & 7;
        reinterpret_cast<float4*>(out + (size_t)stok[n] * CIN + head * 32)[u] =
            reinterpret_cast<const float4*>(sO + n * 36)[u];
    }
}

// ---------------------------------------------------------------------------
extern "C" void kernel_launch(void* const* d_in, const int* in_sizes, int n_in,
                              void* d_out, int out_size) {
    const float* X    = (const float*)d_in[0];   // (32, 3136, 384)
    const float* Wqkv = (const float*)d_in[1];   // (1152, 384)
    const float* bqkv = (const float*)d_in[2];   // (1152,)
    const float* lw   = (const float*)d_in[3];   // (384,1,3,3)
    const float* lb   = (const float*)d_in[4];   // (384,)
    float* out = (float*)d_out;

    cudaFuncSetAttribute(qkv_gemm_mma,
                         cudaFuncAttributeMaxDynamicSharedMemorySize, SMEM_TOTAL_G);

    win_setup<<<64, 49>>>();
    cvt_f16<<<(TOK * CIN / 4) / 256, 256>>>(X, TOK * CIN / 4, 0);
    cvt_f16<<<(COUT * CIN / 4) / 256, 256>>>(Wqkv, COUT * CIN / 4, 1);
    qkv_gemm_mma<<<dim3(COUT / GBN, TOK / GBM), 256, SMEM_TOTAL_G>>>(bqkv);
    attn_kernel<<<dim3(NWIN, NHEAD), 128>>>(lw, lb, out);
}